// round 12
// baseline (speedup 1.0000x reference)
#include <cuda_runtime.h>
#include <cuda_bf16.h>
#include <cstdint>

#define L_ 512
#define T_ 64
#define H_ 512
#define B_ 64
#define E_ 256
#define W_ 256
#define V_ 10000
#define G_ 2048
#define NB 128

// ---- static scratch ----
__device__ float d_emb_proj[(size_t)V_ * G_];
__device__ float d_enc[(size_t)L_ * H_ * B_];     // [t][h][b] fp32
__device__ __nv_bfloat16 d_blend1_bf[(size_t)L_ * B_ * W_];  // [l][b][w] bf16
__device__ float d_dhT[2][H_ * B_];               // [h][b] fp32 (decoder)
__device__ float d_blend2[B_ * W_];
__device__ float d_scores[B_ * L_];
__device__ unsigned d_count;
__device__ unsigned d_gen;
// packed h B-fragments (bf16 hi/lo), double buffered: [chunk32][term2][nt8][reg2][lane32] u32
__device__ uint32_t d_eBp[2][32768];
__device__ uint32_t d_dBp[2][32768];

// SMEM maps (bytes)
#define SMO_FRAG  0          // 131072
#define SMO_PSUM  131072     // 32768
#define SMO_GSH   163840     // 16*65*4 = 4160
#define SMO_IDSA  168000     // encoder ids
#define SMO_IDSB  168256
#define ENC_SMEM  168512
#define SMO_W2SH  168000     // decoder: 4096
#define SMO_PSUMB 172096     // 8192 (32*64 floats)
#define SMO_W2BS  180288
#define SMO_BIAS  180296
#define DEC_SMEM  180368

__device__ __forceinline__ float sigf(float x) { return 1.0f / (1.0f + __expf(-x)); }
__device__ __forceinline__ float tanh_acc(float x) {
    float e = __expf(2.0f * x);
    return 1.0f - 2.0f / (e + 1.0f);
}
__device__ __forceinline__ float tanh_fast(float x) {
    float r; asm("tanh.approx.f32 %0, %1;" : "=f"(r) : "f"(x)); return r;
}
__device__ __forceinline__ unsigned short bfhi(float x) {
    return __bfloat16_as_ushort(__float2bfloat16_rn(x));
}
__device__ __forceinline__ float bf2f(unsigned short u) {
    return __bfloat162float(__ushort_as_bfloat16(u));
}

__device__ __forceinline__ unsigned ld_gen_acq() {
    unsigned v;
    asm volatile("ld.acquire.gpu.global.u32 %0, [%1];" : "=r"(v) : "l"(&d_gen) : "memory");
    return v;
}
__device__ __forceinline__ void grid_barrier(unsigned target) {
    __syncthreads();
    if (threadIdx.x == 0) {
        unsigned prev;
        asm volatile("atom.add.release.gpu.global.u32 %0, [%1], 1;"
                     : "=r"(prev) : "l"(&d_count) : "memory");
        if (prev + 1 == target * NB) {
            asm volatile("st.release.gpu.global.u32 [%0], %1;"
                         :: "l"(&d_gen), "r"(target) : "memory");
        } else {
            while (ld_gen_acq() < target) { __nanosleep(32); }
        }
    }
    __syncthreads();
}

// D(16x8,f32) += A(16x16 bf16, row) x B(16x8 bf16, col)
__device__ __forceinline__ void mma_bf16(float* d, const uint32_t* a, uint32_t b0, uint32_t b1) {
    asm volatile(
        "mma.sync.aligned.m16n8k16.row.col.f32.bf16.bf16.f32 "
        "{%0,%1,%2,%3}, {%4,%5,%6,%7}, {%8,%9}, {%0,%1,%2,%3};"
        : "+f"(d[0]), "+f"(d[1]), "+f"(d[2]), "+f"(d[3])
        : "r"(a[0]), "r"(a[1]), "r"(a[2]), "r"(a[3]), "r"(b0), "r"(b1));
}

// Preload W fragments (A operand), hi/lo bf16. Warp w owns chunks {w, w+8, w+16, w+24}.
__device__ __forceinline__ void preload_A(const float* __restrict__ Whh, int blk,
                                          int w, int g, int tig,
                                          uint32_t Ahi[4][4], uint32_t Alo[4][4]) {
#pragma unroll
    for (int i = 0; i < 4; i++) {
        const int c = w + 8 * i;
#pragma unroll
        for (int half = 0; half < 2; half++) {
            const int k = c * 16 + 2 * tig + half * 8;
#pragma unroll
            for (int rr = 0; rr < 2; rr++) {
                const int r = g + rr * 8;
                const int j = (r >> 2) * 512 + blk * 4 + (r & 3);
                float x0 = __ldg(Whh + (size_t)j * H_ + k);
                float x1 = __ldg(Whh + (size_t)j * H_ + k + 1);
                unsigned short h0 = bfhi(x0), h1 = bfhi(x1);
                unsigned short l0 = bfhi(x0 - bf2f(h0)), l1 = bfhi(x1 - bf2f(h1));
                Ahi[i][half * 2 + rr] = (uint32_t)h0 | ((uint32_t)h1 << 16);
                Alo[i][half * 2 + rr] = (uint32_t)l0 | ((uint32_t)l1 << 16);
            }
        }
    }
}

// Stage 128KB packed fragments in 4 commit groups (8 chunks each).
__device__ __forceinline__ void stage_frag4(const uint32_t* __restrict__ src,
                                            uint32_t smfrag, int tid) {
    const float4* s4 = (const float4*)src;
#pragma unroll
    for (int gct = 0; gct < 4; gct++) {
#pragma unroll
        for (int i = 0; i < 8; i++) {
            int idx = (gct * 8 + i) * 256 + tid;
            asm volatile("cp.async.cg.shared.global [%0], [%1], 16;"
                         :: "r"(smfrag + idx * 16), "l"(s4 + idx));
        }
        asm volatile("cp.async.commit_group;");
    }
}

// Full gates GEMM: interleave 4-group staging with per-chunk compute.
__device__ __forceinline__ void gates_mma(const uint32_t* frag, int w, int lane,
                                          const uint32_t Ahi[4][4], const uint32_t Alo[4][4],
                                          float D[8][4]) {
#pragma unroll
    for (int i = 0; i < 4; i++) {
        if (i == 0)      asm volatile("cp.async.wait_group 3;" ::: "memory");
        else if (i == 1) asm volatile("cp.async.wait_group 2;" ::: "memory");
        else if (i == 2) asm volatile("cp.async.wait_group 1;" ::: "memory");
        else             asm volatile("cp.async.wait_group 0;" ::: "memory");
        __syncthreads();
        const uint32_t* fb = frag + (w + 8 * i) * 1024;
#pragma unroll
        for (int nt = 0; nt < 8; nt++) {
            uint32_t bh0 = fb[nt * 64 + lane];
            uint32_t bh1 = fb[nt * 64 + 32 + lane];
            uint32_t bl0 = fb[512 + nt * 64 + lane];
            uint32_t bl1 = fb[512 + nt * 64 + 32 + lane];
            mma_bf16(D[nt], Ahi[i], bh0, bh1);
            mma_bf16(D[nt], Ahi[i], bl0, bl1);
            mma_bf16(D[nt], Alo[i], bh0, bh1);
        }
    }
}

// Producer: pack this step's 4 h values (cells 0..3, batch b) into B-fragment layout.
__device__ __forceinline__ void pack_h(uint32_t* __restrict__ dst, int blk, int b,
                                       const float* hv) {
    const int chunk = blk >> 2, q = blk & 3;
    const int reg = (q >= 2) ? 1 : 0;
    const int p0 = q * 2;
    const int tig0 = p0 & 3, tig1 = (p0 + 1) & 3;
    const int lb = (b & 7) * 4;
    unsigned short h[4], l[4];
#pragma unroll
    for (int c2 = 0; c2 < 4; c2++) {
        h[c2] = bfhi(hv[c2]);
        l[c2] = bfhi(hv[c2] - bf2f(h[c2]));
    }
    const uint32_t base = chunk * 1024 + (b >> 3) * 64 + reg * 32;
    dst[base + lb + tig0]       = (uint32_t)h[0] | ((uint32_t)h[1] << 16);
    dst[base + 512 + lb + tig0] = (uint32_t)l[0] | ((uint32_t)l[1] << 16);
    dst[base + lb + tig1]       = (uint32_t)h[2] | ((uint32_t)h[3] << 16);
    dst[base + 512 + lb + tig1] = (uint32_t)l[2] | ((uint32_t)l[3] << 16);
}

// Store per-warp D partials and reduce across 8 warps into gsh[r*65+b].
__device__ __forceinline__ void reduce_gates(float* psum, float* gsh, float D[8][4],
                                             int w, int g, int tig, int tid) {
#pragma unroll
    for (int nt = 0; nt < 8; nt++) {
        *(float2*)&psum[(w * 16 + g) * 64 + nt * 8 + 2 * tig]     = make_float2(D[nt][0], D[nt][1]);
        *(float2*)&psum[(w * 16 + g + 8) * 64 + nt * 8 + 2 * tig] = make_float2(D[nt][2], D[nt][3]);
    }
    __syncthreads();
    const int rr = tid >> 4, b4 = (tid & 15) * 4;
    float4 acc = *(const float4*)&psum[rr * 64 + b4];
#pragma unroll
    for (int w2 = 1; w2 < 8; w2++) {
        float4 v = *(const float4*)&psum[(w2 * 16 + rr) * 64 + b4];
        acc.x += v.x; acc.y += v.y; acc.z += v.z; acc.w += v.w;
    }
    gsh[rr * 65 + b4 + 0] = acc.x;
    gsh[rr * 65 + b4 + 1] = acc.y;
    gsh[rr * 65 + b4 + 2] = acc.z;
    gsh[rr * 65 + b4 + 3] = acc.w;
    __syncthreads();
}

// ============ K1: emb_proj = emb @ Wih^T + bih + bhh ============
__global__ void __launch_bounds__(256) k_embproj(
    const float* __restrict__ emb, const float* __restrict__ Wih,
    const float* __restrict__ bih, const float* __restrict__ bhh)
{
    __shared__ __align__(16) float Ash[32 * 68];
    __shared__ __align__(16) float Bsh[32 * 68];
    const int tid = threadIdx.x;
    const int j0 = blockIdx.x * 64, v0 = blockIdx.y * 64;
    const int li = tid >> 2, kk0 = (tid & 3) * 8;
    const int vi0 = (tid & 15) * 4, ji0 = (tid >> 4) * 4;

    float acc[4][4];
#pragma unroll
    for (int i = 0; i < 4; i++)
#pragma unroll
        for (int jj = 0; jj < 4; jj++) acc[i][jj] = 0.0f;

    for (int kt = 0; kt < 8; kt++) {
        const int k0 = kt * 32;
        float4 x0, x1;
        const int v = v0 + li;
        if (v < V_) {
            const float4* ap = (const float4*)(emb + (size_t)v * E_ + k0 + kk0);
            x0 = __ldg(ap); x1 = __ldg(ap + 1);
        } else { x0 = make_float4(0.f,0.f,0.f,0.f); x1 = x0; }
        Ash[(kk0+0)*68+li]=x0.x; Ash[(kk0+1)*68+li]=x0.y; Ash[(kk0+2)*68+li]=x0.z; Ash[(kk0+3)*68+li]=x0.w;
        Ash[(kk0+4)*68+li]=x1.x; Ash[(kk0+5)*68+li]=x1.y; Ash[(kk0+6)*68+li]=x1.z; Ash[(kk0+7)*68+li]=x1.w;
        const float4* bp = (const float4*)(Wih + (size_t)(j0+li) * E_ + k0 + kk0);
        float4 y0 = __ldg(bp), y1 = __ldg(bp + 1);
        Bsh[(kk0+0)*68+li]=y0.x; Bsh[(kk0+1)*68+li]=y0.y; Bsh[(kk0+2)*68+li]=y0.z; Bsh[(kk0+3)*68+li]=y0.w;
        Bsh[(kk0+4)*68+li]=y1.x; Bsh[(kk0+5)*68+li]=y1.y; Bsh[(kk0+6)*68+li]=y1.z; Bsh[(kk0+7)*68+li]=y1.w;
        __syncthreads();
#pragma unroll
        for (int kk = 0; kk < 32; kk++) {
            float4 av = *(const float4*)&Ash[kk*68 + vi0];
            float4 bv = *(const float4*)&Bsh[kk*68 + ji0];
            acc[0][0]=fmaf(av.x,bv.x,acc[0][0]); acc[0][1]=fmaf(av.x,bv.y,acc[0][1]);
            acc[0][2]=fmaf(av.x,bv.z,acc[0][2]); acc[0][3]=fmaf(av.x,bv.w,acc[0][3]);
            acc[1][0]=fmaf(av.y,bv.x,acc[1][0]); acc[1][1]=fmaf(av.y,bv.y,acc[1][1]);
            acc[1][2]=fmaf(av.y,bv.z,acc[1][2]); acc[1][3]=fmaf(av.y,bv.w,acc[1][3]);
            acc[2][0]=fmaf(av.z,bv.x,acc[2][0]); acc[2][1]=fmaf(av.z,bv.y,acc[2][1]);
            acc[2][2]=fmaf(av.z,bv.z,acc[2][2]); acc[2][3]=fmaf(av.z,bv.w,acc[2][3]);
            acc[3][0]=fmaf(av.w,bv.x,acc[3][0]); acc[3][1]=fmaf(av.w,bv.y,acc[3][1]);
            acc[3][2]=fmaf(av.w,bv.z,acc[3][2]); acc[3][3]=fmaf(av.w,bv.w,acc[3][3]);
        }
        __syncthreads();
    }
    float bj[4];
#pragma unroll
    for (int jj = 0; jj < 4; jj++)
        bj[jj] = __ldg(bih + j0 + ji0 + jj) + __ldg(bhh + j0 + ji0 + jj);
#pragma unroll
    for (int ii = 0; ii < 4; ii++) {
        const int v = v0 + vi0 + ii;
        if (v < V_) {
            float4 o = make_float4(acc[ii][0]+bj[0], acc[ii][1]+bj[1],
                                   acc[ii][2]+bj[2], acc[ii][3]+bj[3]);
            *(float4*)&d_emb_proj[(size_t)v * G_ + j0 + ji0] = o;
        }
    }
}

// ============ K2: persistent encoder (mma.sync bf16 hi/lo, 4-group pipeline) ============
__global__ void __launch_bounds__(256, 1) k_encoder(
    const int* __restrict__ ids, const float* __restrict__ Whh)
{
    extern __shared__ __align__(16) char sm[];
    uint32_t* frag = (uint32_t*)(sm + SMO_FRAG);
    float*    psum = (float*)(sm + SMO_PSUM);
    float*    gsh  = (float*)(sm + SMO_GSH);
    int*      idsA = (int*)(sm + SMO_IDSA);
    int*      idsB = (int*)(sm + SMO_IDSB);

    const int tid = threadIdx.x, blk = blockIdx.x;
    const int lane = tid & 31, w = tid >> 5;
    const int g = lane >> 2, tig = lane & 3;
    const uint32_t smfrag = (uint32_t)__cvta_generic_to_shared(frag);
    unsigned g0 = 0;
    if (tid == 0) g0 = ld_gen_acq();

    uint32_t Ahi[4][4], Alo[4][4];
    preload_A(Whh, blk, w, g, tig, Ahi, Alo);
    if (tid < 64) idsA[tid] = __ldg(ids + tid * L_);
    float cc[4] = {0.f, 0.f, 0.f, 0.f};
    __syncthreads();

    for (int t = 0; t < L_; t++) {
        int* cur_ids = (t & 1) ? idsB : idsA;
        int* nxt_ids = (t & 1) ? idsA : idsB;
        if (t > 0) stage_frag4(d_eBp[(t - 1) & 1], smfrag, tid);
        float ei[4], ef[4], eg[4], eo[4];
        if (tid < 64) {
            const float4* ep = (const float4*)(d_emb_proj + (size_t)cur_ids[tid] * G_);
            float4 x0 = __ldg(ep + blk);
            float4 x1 = __ldg(ep + 128 + blk);
            float4 x2 = __ldg(ep + 256 + blk);
            float4 x3 = __ldg(ep + 384 + blk);
            ei[0]=x0.x; ei[1]=x0.y; ei[2]=x0.z; ei[3]=x0.w;
            ef[0]=x1.x; ef[1]=x1.y; ef[2]=x1.z; ef[3]=x1.w;
            eg[0]=x2.x; eg[1]=x2.y; eg[2]=x2.z; eg[3]=x2.w;
            eo[0]=x3.x; eo[1]=x3.y; eo[2]=x3.z; eo[3]=x3.w;
            if (t + 1 < L_) nxt_ids[tid] = __ldg(ids + tid * L_ + t + 1);
        }

        if (t > 0) {
            float D[8][4];
#pragma unroll
            for (int nt = 0; nt < 8; nt++)
#pragma unroll
                for (int i = 0; i < 4; i++) D[nt][i] = 0.0f;
            gates_mma(frag, w, lane, Ahi, Alo, D);
            reduce_gates(psum, gsh, D, w, g, tig, tid);
        }

        if (tid < 64) {
            const int b = tid;
            float hv[4];
#pragma unroll
            for (int cell = 0; cell < 4; cell++) {
                float gi = ((t > 0) ? gsh[(0  + cell) * 65 + b] : 0.f) + ei[cell];
                float gf = ((t > 0) ? gsh[(4  + cell) * 65 + b] : 0.f) + ef[cell];
                float gg = ((t > 0) ? gsh[(8  + cell) * 65 + b] : 0.f) + eg[cell];
                float go = ((t > 0) ? gsh[(12 + cell) * 65 + b] : 0.f) + eo[cell];
                cc[cell] = sigf(gf) * cc[cell] + sigf(gi) * tanh_acc(gg);
                float h = sigf(go) * tanh_acc(cc[cell]);
                d_enc[(size_t)t * H_ * B_ + (blk * 4 + cell) * 64 + b] = h;
                hv[cell] = h;
            }
            pack_h(d_eBp[t & 1], blk, b, hv);
        }
        if (t + 1 < L_) grid_barrier(g0 + t + 1);
    }
}

// ============ K3: blend1 (bf16 output) ============
__global__ void __launch_bounds__(256) k_blend1(
    const float* __restrict__ W1w, const float* __restrict__ W1b)
{
    __shared__ __align__(16) float ensh[32 * 64];
    __shared__ float w1sh[32 * 257];
    const int tid = threadIdx.x, l = blockIdx.x;
    float4 acc[16];
#pragma unroll
    for (int g = 0; g < 16; g++) acc[g] = make_float4(0.f,0.f,0.f,0.f);

    for (int ht = 0; ht < 16; ht++) {
        const float4* ep = (const float4*)(d_enc + (size_t)l * H_ * B_ + (size_t)ht * 32 * 64);
        ((float4*)ensh)[tid]       = __ldg(ep + tid);
        ((float4*)ensh)[tid + 256] = __ldg(ep + tid + 256);
#pragma unroll
        for (int rep = 0; rep < 32; rep++) {
            const int lin = rep * 256 + tid;
            const int w = lin >> 5, hh = lin & 31;
            w1sh[hh * 257 + w] = __ldg(W1w + (size_t)w * H_ + ht * 32 + hh);
        }
        __syncthreads();
#pragma unroll
        for (int hh = 0; hh < 32; hh++) {
            const float wv = w1sh[hh * 257 + tid];
            const float4* e4 = (const float4*)(ensh + hh * 64);
#pragma unroll
            for (int g = 0; g < 16; g++) {
                float4 ev = e4[g];
                acc[g].x = fmaf(wv, ev.x, acc[g].x);
                acc[g].y = fmaf(wv, ev.y, acc[g].y);
                acc[g].z = fmaf(wv, ev.z, acc[g].z);
                acc[g].w = fmaf(wv, ev.w, acc[g].w);
            }
        }
        __syncthreads();
    }
    const float bias = __ldg(W1b + tid);
    __nv_bfloat16* outp = d_blend1_bf + (size_t)l * B_ * W_ + tid;
#pragma unroll
    for (int g = 0; g < 16; g++) {
        outp[(g*4+0) * W_] = __float2bfloat16_rn(acc[g].x + bias);
        outp[(g*4+1) * W_] = __float2bfloat16_rn(acc[g].y + bias);
        outp[(g*4+2) * W_] = __float2bfloat16_rn(acc[g].z + bias);
        outp[(g*4+3) * W_] = __float2bfloat16_rn(acc[g].w + bias);
    }
}

// ============ K4: persistent decoder ============
__global__ void __launch_bounds__(256, 1) k_decoder(
    const float* __restrict__ Whh, const float* __restrict__ bih,
    const float* __restrict__ bhh, const float* __restrict__ W2w,
    const float* __restrict__ W2b, const float* __restrict__ vtw,
    const float* __restrict__ h0, float* __restrict__ out)
{
    extern __shared__ __align__(16) char sm[];
    uint32_t* frag  = (uint32_t*)(sm + SMO_FRAG);
    float*    psum  = (float*)(sm + SMO_PSUM);
    float*    gsh   = (float*)(sm + SMO_GSH);
    float*    w2sh  = (float*)(sm + SMO_W2SH);
    float*    psumB = (float*)(sm + SMO_PSUMB);
    float*    w2bs  = (float*)(sm + SMO_W2BS);
    float*    bias_sh = (float*)(sm + SMO_BIAS);

    const int tid = threadIdx.x, blk = blockIdx.x;
    const int lane = tid & 31, w = tid >> 5;
    const int g = lane >> 2, tig = lane & 3;
    const uint32_t smfrag = (uint32_t)__cvta_generic_to_shared(frag);
    unsigned g0 = 0;
    if (tid == 0) g0 = ld_gen_acq();

    uint32_t Ahi[4][4], Alo[4][4];
    preload_A(Whh, blk, w, g, tig, Ahi, Alo);
    if (tid < 16) {
        const int j = (tid >> 2) * 512 + blk * 4 + (tid & 3);
        bias_sh[tid] = __ldg(bih + j) + __ldg(bhh + j);
    }
    for (int idx = tid; idx < 1024; idx += 256) {
        const int row = idx >> 9, hh = idx & 511;
        w2sh[idx] = __ldg(W2w + (size_t)(2 * blk + row) * H_ + hh);
    }
    if (tid < 2) w2bs[tid] = __ldg(W2b + 2 * blk + tid);
    float cc[4] = {0.f, 0.f, 0.f, 0.f};
    if (tid < 64) {
        float hv[4];
#pragma unroll
        for (int cell = 0; cell < 4; cell++) {
            float x = __ldg(h0 + (size_t)tid * H_ + blk * 4 + cell);
            d_dhT[0][(blk * 4 + cell) * 64 + tid] = x;
            hv[cell] = x;
            cc[cell] = __ldg(d_enc + (size_t)(L_ - 1) * H_ * B_ + (blk * 4 + cell) * 64 + tid);
        }
        pack_h(d_dBp[0], blk, tid, hv);
    }
    const int wrp = w;
    const int gw = blk * 8 + wrp;
    const int cb = gw & 63, lbase = (gw >> 6) * 32;
    const float4 vta = __ldg((const float4*)vtw + 2 * lane);
    const float4 vtb = __ldg((const float4*)vtw + 2 * lane + 1);
    const int pks = tid >> 4, pbg = tid & 15;

    grid_barrier(g0 + 1);
    const unsigned base = g0 + 1;

    for (int s = 0; s < T_; s++) {
        const int cur = s & 1, nxt = cur ^ 1;

        // ---- A: recurrent gates via mma.sync (4-group pipeline) ----
        {
            stage_frag4(d_dBp[cur], smfrag, tid);
            float D[8][4];
#pragma unroll
            for (int nt = 0; nt < 8; nt++)
#pragma unroll
                for (int i = 0; i < 4; i++) D[nt][i] = 0.0f;
            gates_mma(frag, w, lane, Ahi, Alo, D);
            reduce_gates(psum, gsh, D, w, g, tig, tid);
        }
        if (tid < 64) {
            const int b = tid;
            float hv[4];
#pragma unroll
            for (int cell = 0; cell < 4; cell++) {
                float gi = gsh[(0  + cell) * 65 + b] + bias_sh[cell];
                float gf = gsh[(4  + cell) * 65 + b] + bias_sh[4 + cell];
                float gg = gsh[(8  + cell) * 65 + b] + bias_sh[8 + cell];
                float go = gsh[(12 + cell) * 65 + b] + bias_sh[12 + cell];
                cc[cell] = sigf(gf) * cc[cell] + sigf(gi) * tanh_acc(gg);
                float h = sigf(go) * tanh_acc(cc[cell]);
                d_dhT[nxt][(blk * 4 + cell) * 64 + b] = h;
                hv[cell] = h;
            }
            pack_h(d_dBp[nxt], blk, b, hv);
        }
        grid_barrier(base + 3 * s + 1);

        // ---- B: blend2 rows 2*blk, 2*blk+1 (dedup: each h tile read once) ----
        {
            const float4* hp4 = (const float4*)d_dhT[nxt] + pbg;
            const float* wp0 = w2sh + pks * 32;
            const float* wp1 = w2sh + 512 + pks * 32;
            float4 a0 = make_float4(0.f, 0.f, 0.f, 0.f);
            float4 a1 = make_float4(0.f, 0.f, 0.f, 0.f);
#pragma unroll 8
            for (int k = 0; k < 32; k++) {
                float4 hv = __ldg(hp4 + (size_t)(pks * 32 + k) * 16);
                float w0 = wp0[k], w1 = wp1[k];
                a0.x = fmaf(w0, hv.x, a0.x); a0.y = fmaf(w0, hv.y, a0.y);
                a0.z = fmaf(w0, hv.z, a0.z); a0.w = fmaf(w0, hv.w, a0.w);
                a1.x = fmaf(w1, hv.x, a1.x); a1.y = fmaf(w1, hv.y, a1.y);
                a1.z = fmaf(w1, hv.z, a1.z); a1.w = fmaf(w1, hv.w, a1.w);
            }
            *(float4*)&psumB[(pks * 2 + 0) * 64 + pbg * 4] = a0;
            *(float4*)&psumB[(pks * 2 + 1) * 64 + pbg * 4] = a1;
        }
        __syncthreads();
        if (tid < 128) {
            const int b = tid & 63, wl = tid >> 6;
            float sacc = w2bs[wl];
#pragma unroll
            for (int ks = 0; ks < 16; ks++) sacc += psumB[(ks * 2 + wl) * 64 + b];
            d_blend2[b * 256 + 2 * blk + wl] = sacc;
        }
        grid_barrier(base + 3 * s + 2);

        // ---- C: scores[b][l] = tanh(blend1_bf + blend2) . vt  (bf16 blend1) ----
        {
            float4 b2a = __ldcg((const float4*)(d_blend2 + cb * 256) + 2 * lane);
            float4 b2b = __ldcg((const float4*)(d_blend2 + cb * 256) + 2 * lane + 1);
            for (int li = 0; li < 32; li++) {
                const int l = lbase + li;
                uint4 p = __ldg((const uint4*)(d_blend1_bf + ((size_t)l * 64 + cb) * 256) + lane);
                float f0 = bf2f((unsigned short)(p.x & 0xFFFF));
                float f1 = bf2f((unsigned short)(p.x >> 16));
                float f2 = bf2f((unsigned short)(p.y & 0xFFFF));
                float f3 = bf2f((unsigned short)(p.y >> 16));
                float f4 = bf2f((unsigned short)(p.z & 0xFFFF));
                float f5 = bf2f((unsigned short)(p.z >> 16));
                float f6 = bf2f((unsigned short)(p.w & 0xFFFF));
                float f7 = bf2f((unsigned short)(p.w >> 16));
                float sv = tanh_fast(f0 + b2a.x) * vta.x + tanh_fast(f1 + b2a.y) * vta.y
                         + tanh_fast(f2 + b2a.z) * vta.z + tanh_fast(f3 + b2a.w) * vta.w
                         + tanh_fast(f4 + b2b.x) * vtb.x + tanh_fast(f5 + b2b.y) * vtb.y
                         + tanh_fast(f6 + b2b.z) * vtb.z + tanh_fast(f7 + b2b.w) * vtb.w;
#pragma unroll
                for (int o = 16; o > 0; o >>= 1) sv += __shfl_xor_sync(0xFFFFFFFFu, sv, o);
                if (lane == 0) d_scores[cb * 512 + l] = sv;
            }
        }
        grid_barrier(base + 3 * s + 3);

        // ---- D: log-softmax over l (shuffle reduction), out[l][b][s] ----
        if (blk < 64) {
            float* red = psumB;
            const int b = blk;
            float s0 = __ldcg(d_scores + b * 512 + tid);
            float s1 = __ldcg(d_scores + b * 512 + tid + 256);
            float m = fmaxf(s0, s1);
#pragma unroll
            for (int o = 16; o > 0; o >>= 1) m = fmaxf(m, __shfl_xor_sync(0xFFFFFFFFu, m, o));
            if (lane == 0) red[wrp] = m;
            __syncthreads();
            float mm = red[0];
#pragma unroll
            for (int i = 1; i < 8; i++) mm = fmaxf(mm, red[i]);
            float se = __expf(s0 - mm) + __expf(s1 - mm);
#pragma unroll
            for (int o = 16; o > 0; o >>= 1) se += __shfl_xor_sync(0xFFFFFFFFu, se, o);
            if (lane == 0) red[8 + wrp] = se;
            __syncthreads();
            float tot = red[8];
#pragma unroll
            for (int i = 9; i < 16; i++) tot += red[i];
            const float lse = mm + __logf(tot);
            out[((size_t)tid         * 64 + b) * 64 + s] = s0 - lse;
            out[((size_t)(tid + 256) * 64 + b) * 64 + s] = s1 - lse;
        }
        __syncthreads();
    }
}

extern "C" void kernel_launch(void* const* d_in, const int* in_sizes, int n_in,
                              void* d_out, int out_size) {
    const int*   ids  = (const int*)  d_in[0];
    const float* emb  = (const float*)d_in[1];
    const float* eWih = (const float*)d_in[2];
    const float* eWhh = (const float*)d_in[3];
    const float* ebih = (const float*)d_in[4];
    const float* ebhh = (const float*)d_in[5];
    const float* dWhh = (const float*)d_in[7];
    const float* dbih = (const float*)d_in[8];
    const float* dbhh = (const float*)d_in[9];
    const float* W1w  = (const float*)d_in[10];
    const float* W1b  = (const float*)d_in[11];
    const float* W2w  = (const float*)d_in[12];
    const float* W2b  = (const float*)d_in[13];
    const float* vtw  = (const float*)d_in[14];
    const float* h0   = (const float*)d_in[16];
    float* out = (float*)d_out;

    cudaFuncSetAttribute(k_encoder, cudaFuncAttributeMaxDynamicSharedMemorySize, ENC_SMEM);
    cudaFuncSetAttribute(k_decoder, cudaFuncAttributeMaxDynamicSharedMemorySize, DEC_SMEM);

    dim3 g1(G_ / 64, (V_ + 63) / 64);
    k_embproj<<<g1, 256>>>(emb, eWih, ebih, ebhh);
    k_encoder<<<NB, 256, ENC_SMEM>>>(ids, eWhh);
    k_blend1<<<L_, 256>>>(W1w, W1b);
    k_decoder<<<NB, 256, DEC_SMEM>>>(dWhh, dbih, dbhh, W2w, W2b, vtw, h0, out);
}

// round 13
// speedup vs baseline: 1.0188x; 1.0188x over previous
#include <cuda_runtime.h>
#include <cuda_fp16.h>
#include <cstdint>

#define L_ 512
#define T_ 64
#define H_ 512
#define B_ 64
#define E_ 256
#define W_ 256
#define V_ 10000
#define G_ 2048
#define NB 128

// ---- static scratch ----
__device__ float d_emb_proj[(size_t)V_ * G_];
__device__ float d_enc[(size_t)L_ * H_ * B_];     // [t][h][b] fp32
__device__ float d_blend1[(size_t)L_ * B_ * W_];  // [l][b][w] fp32
__device__ float d_dhT[2][H_ * B_];               // [h][b] fp32 (decoder)
__device__ float d_blend2[B_ * W_];
__device__ float d_scores[B_ * L_];
__device__ unsigned d_count;
__device__ unsigned d_gen;
// packed h B-fragments (single fp16), double buffered: [chunk32][nt8][reg2][lane32] u32
__device__ uint32_t d_eBp[2][16384];
__device__ uint32_t d_dBp[2][16384];

// SMEM maps (bytes)
#define SMO_FRAG  0          // 65536
#define SMO_PSUM  65536      // 32768
#define SMO_GSH   98304      // 16*65*4 = 4160
#define SMO_IDSA  102464     // encoder ids
#define SMO_IDSB  102720
#define ENC_SMEM  102976
#define SMO_W2SH  102464     // decoder: 4096
#define SMO_PSUMB 106560     // 4096
#define SMO_W2BS  110656     // 8
#define SMO_BIAS  110664     // 64
#define DEC_SMEM  110728

__device__ __forceinline__ float sigf(float x) { return 1.0f / (1.0f + __expf(-x)); }
__device__ __forceinline__ float tanh_acc(float x) {
    float e = __expf(2.0f * x);
    return 1.0f - 2.0f / (e + 1.0f);
}
__device__ __forceinline__ float tanh_fast(float x) {
    float r; asm("tanh.approx.f32 %0, %1;" : "=f"(r) : "f"(x)); return r;
}
__device__ __forceinline__ unsigned short fphi(float x) {
    return __half_as_ushort(__float2half_rn(x));
}
__device__ __forceinline__ float fp2f(unsigned short u) {
    return __half2float(__ushort_as_half(u));
}

__device__ __forceinline__ unsigned ld_gen_acq() {
    unsigned v;
    asm volatile("ld.acquire.gpu.global.u32 %0, [%1];" : "=r"(v) : "l"(&d_gen) : "memory");
    return v;
}
__device__ __forceinline__ void grid_barrier(unsigned target) {
    __syncthreads();
    if (threadIdx.x == 0) {
        unsigned prev;
        asm volatile("atom.add.release.gpu.global.u32 %0, [%1], 1;"
                     : "=r"(prev) : "l"(&d_count) : "memory");
        if (prev + 1 == target * NB) {
            asm volatile("st.release.gpu.global.u32 [%0], %1;"
                         :: "l"(&d_gen), "r"(target) : "memory");
        } else {
            while (ld_gen_acq() < target) { __nanosleep(32); }
        }
    }
    __syncthreads();
}

// D(16x8,f32) += A(16x16 fp16, row) x B(16x8 fp16, col)
__device__ __forceinline__ void mma_fp16(float* d, const uint32_t* a, uint32_t b0, uint32_t b1) {
    asm volatile(
        "mma.sync.aligned.m16n8k16.row.col.f32.f16.f16.f32 "
        "{%0,%1,%2,%3}, {%4,%5,%6,%7}, {%8,%9}, {%0,%1,%2,%3};"
        : "+f"(d[0]), "+f"(d[1]), "+f"(d[2]), "+f"(d[3])
        : "r"(a[0]), "r"(a[1]), "r"(a[2]), "r"(a[3]), "r"(b0), "r"(b1));
}

// Preload W fragments (A operand), fp16 hi/lo. Warp w owns chunks {w, w+8, w+16, w+24}.
__device__ __forceinline__ void preload_A(const float* __restrict__ Whh, int blk,
                                          int w, int g, int tig,
                                          uint32_t Ahi[4][4], uint32_t Alo[4][4]) {
#pragma unroll
    for (int i = 0; i < 4; i++) {
        const int c = w + 8 * i;
#pragma unroll
        for (int half = 0; half < 2; half++) {
            const int k = c * 16 + 2 * tig + half * 8;
#pragma unroll
            for (int rr = 0; rr < 2; rr++) {
                const int r = g + rr * 8;
                const int j = (r >> 2) * 512 + blk * 4 + (r & 3);
                float x0 = __ldg(Whh + (size_t)j * H_ + k);
                float x1 = __ldg(Whh + (size_t)j * H_ + k + 1);
                unsigned short h0 = fphi(x0), h1 = fphi(x1);
                unsigned short l0 = fphi(x0 - fp2f(h0)), l1 = fphi(x1 - fp2f(h1));
                Ahi[i][half * 2 + rr] = (uint32_t)h0 | ((uint32_t)h1 << 16);
                Alo[i][half * 2 + rr] = (uint32_t)l0 | ((uint32_t)l1 << 16);
            }
        }
    }
}

// Stage 64KB packed fragments in 2 commit groups (chunks 0-15, 16-31).
__device__ __forceinline__ void stage_frag(const uint32_t* __restrict__ src,
                                           uint32_t smfrag, int tid) {
    const float4* s4 = (const float4*)src;
#pragma unroll
    for (int i = 0; i < 8; i++) {
        int idx = i * 256 + tid;
        asm volatile("cp.async.cg.shared.global [%0], [%1], 16;"
                     :: "r"(smfrag + idx * 16), "l"(s4 + idx));
    }
    asm volatile("cp.async.commit_group;");
#pragma unroll
    for (int i = 8; i < 16; i++) {
        int idx = i * 256 + tid;
        asm volatile("cp.async.cg.shared.global [%0], [%1], 16;"
                     :: "r"(smfrag + idx * 16), "l"(s4 + idx));
    }
    asm volatile("cp.async.commit_group;");
}

// MMA over 2 chunks starting at group i0 (i0=0 covers chunks {w, w+8}).
__device__ __forceinline__ void compute_group(const uint32_t* frag, int w, int lane, int i0,
                                              const uint32_t Ahi[4][4], const uint32_t Alo[4][4],
                                              float D[8][4]) {
#pragma unroll
    for (int ii = 0; ii < 2; ii++) {
        const int i = i0 + ii;
        const uint32_t* fb = frag + (w + 8 * i) * 512;
#pragma unroll
        for (int nt = 0; nt < 8; nt++) {
            uint32_t b0 = fb[nt * 64 + lane];
            uint32_t b1 = fb[nt * 64 + 32 + lane];
            mma_fp16(D[nt], Ahi[i], b0, b1);
            mma_fp16(D[nt], Alo[i], b0, b1);
        }
    }
}

// Producer: pack this step's 4 h values (cells 0..3, batch b) as fp16 fragments.
__device__ __forceinline__ void pack_h(uint32_t* __restrict__ dst, int blk, int b,
                                       const float* hv) {
    const int chunk = blk >> 2, q = blk & 3;
    const int reg = (q >= 2) ? 1 : 0;
    const int p0 = q * 2;
    const int tig0 = p0 & 3, tig1 = (p0 + 1) & 3;
    const int lb = (b & 7) * 4;
    unsigned short h[4];
#pragma unroll
    for (int c2 = 0; c2 < 4; c2++) h[c2] = fphi(hv[c2]);
    const uint32_t base = chunk * 512 + (b >> 3) * 64 + reg * 32;
    dst[base + lb + tig0] = (uint32_t)h[0] | ((uint32_t)h[1] << 16);
    dst[base + lb + tig1] = (uint32_t)h[2] | ((uint32_t)h[3] << 16);
}

// Store per-warp D partials and reduce across 8 warps into gsh[r*65+b].
__device__ __forceinline__ void reduce_gates(float* psum, float* gsh, float D[8][4],
                                             int w, int g, int tig, int tid) {
#pragma unroll
    for (int nt = 0; nt < 8; nt++) {
        *(float2*)&psum[(w * 16 + g) * 64 + nt * 8 + 2 * tig]     = make_float2(D[nt][0], D[nt][1]);
        *(float2*)&psum[(w * 16 + g + 8) * 64 + nt * 8 + 2 * tig] = make_float2(D[nt][2], D[nt][3]);
    }
    __syncthreads();
    const int rr = tid >> 4, b4 = (tid & 15) * 4;
    float4 acc = *(const float4*)&psum[rr * 64 + b4];
#pragma unroll
    for (int w2 = 1; w2 < 8; w2++) {
        float4 v = *(const float4*)&psum[(w2 * 16 + rr) * 64 + b4];
        acc.x += v.x; acc.y += v.y; acc.z += v.z; acc.w += v.w;
    }
    gsh[rr * 65 + b4 + 0] = acc.x;
    gsh[rr * 65 + b4 + 1] = acc.y;
    gsh[rr * 65 + b4 + 2] = acc.z;
    gsh[rr * 65 + b4 + 3] = acc.w;
    __syncthreads();
}

// ============ K1: emb_proj = emb @ Wih^T + bih + bhh ============
__global__ void __launch_bounds__(256) k_embproj(
    const float* __restrict__ emb, const float* __restrict__ Wih,
    const float* __restrict__ bih, const float* __restrict__ bhh)
{
    __shared__ __align__(16) float Ash[32 * 68];
    __shared__ __align__(16) float Bsh[32 * 68];
    const int tid = threadIdx.x;
    const int j0 = blockIdx.x * 64, v0 = blockIdx.y * 64;
    const int li = tid >> 2, kk0 = (tid & 3) * 8;
    const int vi0 = (tid & 15) * 4, ji0 = (tid >> 4) * 4;

    float acc[4][4];
#pragma unroll
    for (int i = 0; i < 4; i++)
#pragma unroll
        for (int jj = 0; jj < 4; jj++) acc[i][jj] = 0.0f;

    for (int kt = 0; kt < 8; kt++) {
        const int k0 = kt * 32;
        float4 x0, x1;
        const int v = v0 + li;
        if (v < V_) {
            const float4* ap = (const float4*)(emb + (size_t)v * E_ + k0 + kk0);
            x0 = __ldg(ap); x1 = __ldg(ap + 1);
        } else { x0 = make_float4(0.f,0.f,0.f,0.f); x1 = x0; }
        Ash[(kk0+0)*68+li]=x0.x; Ash[(kk0+1)*68+li]=x0.y; Ash[(kk0+2)*68+li]=x0.z; Ash[(kk0+3)*68+li]=x0.w;
        Ash[(kk0+4)*68+li]=x1.x; Ash[(kk0+5)*68+li]=x1.y; Ash[(kk0+6)*68+li]=x1.z; Ash[(kk0+7)*68+li]=x1.w;
        const float4* bp = (const float4*)(Wih + (size_t)(j0+li) * E_ + k0 + kk0);
        float4 y0 = __ldg(bp), y1 = __ldg(bp + 1);
        Bsh[(kk0+0)*68+li]=y0.x; Bsh[(kk0+1)*68+li]=y0.y; Bsh[(kk0+2)*68+li]=y0.z; Bsh[(kk0+3)*68+li]=y0.w;
        Bsh[(kk0+4)*68+li]=y1.x; Bsh[(kk0+5)*68+li]=y1.y; Bsh[(kk0+6)*68+li]=y1.z; Bsh[(kk0+7)*68+li]=y1.w;
        __syncthreads();
#pragma unroll
        for (int kk = 0; kk < 32; kk++) {
            float4 av = *(const float4*)&Ash[kk*68 + vi0];
            float4 bv = *(const float4*)&Bsh[kk*68 + ji0];
            acc[0][0]=fmaf(av.x,bv.x,acc[0][0]); acc[0][1]=fmaf(av.x,bv.y,acc[0][1]);
            acc[0][2]=fmaf(av.x,bv.z,acc[0][2]); acc[0][3]=fmaf(av.x,bv.w,acc[0][3]);
            acc[1][0]=fmaf(av.y,bv.x,acc[1][0]); acc[1][1]=fmaf(av.y,bv.y,acc[1][1]);
            acc[1][2]=fmaf(av.y,bv.z,acc[1][2]); acc[1][3]=fmaf(av.y,bv.w,acc[1][3]);
            acc[2][0]=fmaf(av.z,bv.x,acc[2][0]); acc[2][1]=fmaf(av.z,bv.y,acc[2][1]);
            acc[2][2]=fmaf(av.z,bv.z,acc[2][2]); acc[2][3]=fmaf(av.z,bv.w,acc[2][3]);
            acc[3][0]=fmaf(av.w,bv.x,acc[3][0]); acc[3][1]=fmaf(av.w,bv.y,acc[3][1]);
            acc[3][2]=fmaf(av.w,bv.z,acc[3][2]); acc[3][3]=fmaf(av.w,bv.w,acc[3][3]);
        }
        __syncthreads();
    }
    float bj[4];
#pragma unroll
    for (int jj = 0; jj < 4; jj++)
        bj[jj] = __ldg(bih + j0 + ji0 + jj) + __ldg(bhh + j0 + ji0 + jj);
#pragma unroll
    for (int ii = 0; ii < 4; ii++) {
        const int v = v0 + vi0 + ii;
        if (v < V_) {
            float4 o = make_float4(acc[ii][0]+bj[0], acc[ii][1]+bj[1],
                                   acc[ii][2]+bj[2], acc[ii][3]+bj[3]);
            *(float4*)&d_emb_proj[(size_t)v * G_ + j0 + ji0] = o;
        }
    }
}

// ============ K2: persistent encoder (mma.sync fp16 W-split) ============
__global__ void __launch_bounds__(256, 1) k_encoder(
    const int* __restrict__ ids, const float* __restrict__ Whh)
{
    extern __shared__ __align__(16) char sm[];
    uint32_t* frag = (uint32_t*)(sm + SMO_FRAG);
    float*    psum = (float*)(sm + SMO_PSUM);
    float*    gsh  = (float*)(sm + SMO_GSH);
    int*      idsA = (int*)(sm + SMO_IDSA);
    int*      idsB = (int*)(sm + SMO_IDSB);

    const int tid = threadIdx.x, blk = blockIdx.x;
    const int lane = tid & 31, w = tid >> 5;
    const int g = lane >> 2, tig = lane & 3;
    const uint32_t smfrag = (uint32_t)__cvta_generic_to_shared(frag);
    unsigned g0 = 0;
    if (tid == 0) g0 = ld_gen_acq();

    uint32_t Ahi[4][4], Alo[4][4];
    preload_A(Whh, blk, w, g, tig, Ahi, Alo);
    if (tid < 64) idsA[tid] = __ldg(ids + tid * L_);
    float cc[4] = {0.f, 0.f, 0.f, 0.f};
    __syncthreads();

    for (int t = 0; t < L_; t++) {
        int* cur_ids = (t & 1) ? idsB : idsA;
        int* nxt_ids = (t & 1) ? idsA : idsB;
        if (t > 0) stage_frag(d_eBp[(t - 1) & 1], smfrag, tid);
        float ei[4], ef[4], eg[4], eo[4];
        if (tid < 64) {
            const float4* ep = (const float4*)(d_emb_proj + (size_t)cur_ids[tid] * G_);
            float4 x0 = __ldg(ep + blk);
            float4 x1 = __ldg(ep + 128 + blk);
            float4 x2 = __ldg(ep + 256 + blk);
            float4 x3 = __ldg(ep + 384 + blk);
            ei[0]=x0.x; ei[1]=x0.y; ei[2]=x0.z; ei[3]=x0.w;
            ef[0]=x1.x; ef[1]=x1.y; ef[2]=x1.z; ef[3]=x1.w;
            eg[0]=x2.x; eg[1]=x2.y; eg[2]=x2.z; eg[3]=x2.w;
            eo[0]=x3.x; eo[1]=x3.y; eo[2]=x3.z; eo[3]=x3.w;
            if (t + 1 < L_) nxt_ids[tid] = __ldg(ids + tid * L_ + t + 1);
        }

        if (t > 0) {
            float D[8][4];
#pragma unroll
            for (int nt = 0; nt < 8; nt++)
#pragma unroll
                for (int i = 0; i < 4; i++) D[nt][i] = 0.0f;
            asm volatile("cp.async.wait_group 1;" ::: "memory");
            __syncthreads();
            compute_group(frag, w, lane, 0, Ahi, Alo, D);
            asm volatile("cp.async.wait_group 0;" ::: "memory");
            __syncthreads();
            compute_group(frag, w, lane, 2, Ahi, Alo, D);
            reduce_gates(psum, gsh, D, w, g, tig, tid);
        }

        if (tid < 64) {
            const int b = tid;
            float hv[4];
#pragma unroll
            for (int cell = 0; cell < 4; cell++) {
                float gi = ((t > 0) ? gsh[(0  + cell) * 65 + b] : 0.f) + ei[cell];
                float gf = ((t > 0) ? gsh[(4  + cell) * 65 + b] : 0.f) + ef[cell];
                float gg = ((t > 0) ? gsh[(8  + cell) * 65 + b] : 0.f) + eg[cell];
                float go = ((t > 0) ? gsh[(12 + cell) * 65 + b] : 0.f) + eo[cell];
                cc[cell] = sigf(gf) * cc[cell] + sigf(gi) * tanh_acc(gg);
                float h = sigf(go) * tanh_acc(cc[cell]);
                d_enc[(size_t)t * H_ * B_ + (blk * 4 + cell) * 64 + b] = h;
                hv[cell] = h;
            }
            pack_h(d_eBp[t & 1], blk, b, hv);
        }
        if (t + 1 < L_) grid_barrier(g0 + t + 1);
    }
}

// ============ K3: blend1[l][b][w] = enc[l] @ W1^T + b1 ============
__global__ void __launch_bounds__(256) k_blend1(
    const float* __restrict__ W1w, const float* __restrict__ W1b)
{
    __shared__ __align__(16) float ensh[32 * 64];
    __shared__ float w1sh[32 * 257];
    const int tid = threadIdx.x, l = blockIdx.x;
    float4 acc[16];
#pragma unroll
    for (int g = 0; g < 16; g++) acc[g] = make_float4(0.f,0.f,0.f,0.f);

    for (int ht = 0; ht < 16; ht++) {
        const float4* ep = (const float4*)(d_enc + (size_t)l * H_ * B_ + (size_t)ht * 32 * 64);
        ((float4*)ensh)[tid]       = __ldg(ep + tid);
        ((float4*)ensh)[tid + 256] = __ldg(ep + tid + 256);
#pragma unroll
        for (int rep = 0; rep < 32; rep++) {
            const int lin = rep * 256 + tid;
            const int w = lin >> 5, hh = lin & 31;
            w1sh[hh * 257 + w] = __ldg(W1w + (size_t)w * H_ + ht * 32 + hh);
        }
        __syncthreads();
#pragma unroll
        for (int hh = 0; hh < 32; hh++) {
            const float wv = w1sh[hh * 257 + tid];
            const float4* e4 = (const float4*)(ensh + hh * 64);
#pragma unroll
            for (int g = 0; g < 16; g++) {
                float4 ev = e4[g];
                acc[g].x = fmaf(wv, ev.x, acc[g].x);
                acc[g].y = fmaf(wv, ev.y, acc[g].y);
                acc[g].z = fmaf(wv, ev.z, acc[g].z);
                acc[g].w = fmaf(wv, ev.w, acc[g].w);
            }
        }
        __syncthreads();
    }
    const float bias = __ldg(W1b + tid);
    float* outp = d_blend1 + (size_t)l * B_ * W_ + tid;
#pragma unroll
    for (int g = 0; g < 16; g++) {
        outp[(g*4+0) * W_] = acc[g].x + bias;
        outp[(g*4+1) * W_] = acc[g].y + bias;
        outp[(g*4+2) * W_] = acc[g].z + bias;
        outp[(g*4+3) * W_] = acc[g].w + bias;
    }
}

// ============ K4: persistent decoder ============
__global__ void __launch_bounds__(256, 1) k_decoder(
    const float* __restrict__ Whh, const float* __restrict__ bih,
    const float* __restrict__ bhh, const float* __restrict__ W2w,
    const float* __restrict__ W2b, const float* __restrict__ vtw,
    const float* __restrict__ h0, float* __restrict__ out)
{
    extern __shared__ __align__(16) char sm[];
    uint32_t* frag  = (uint32_t*)(sm + SMO_FRAG);
    float*    psum  = (float*)(sm + SMO_PSUM);
    float*    gsh   = (float*)(sm + SMO_GSH);
    float*    w2sh  = (float*)(sm + SMO_W2SH);
    float*    psumB = (float*)(sm + SMO_PSUMB);
    float*    w2bs  = (float*)(sm + SMO_W2BS);
    float*    bias_sh = (float*)(sm + SMO_BIAS);

    const int tid = threadIdx.x, blk = blockIdx.x;
    const int lane = tid & 31, w = tid >> 5;
    const int g = lane >> 2, tig = lane & 3;
    const uint32_t smfrag = (uint32_t)__cvta_generic_to_shared(frag);
    unsigned g0 = 0;
    if (tid == 0) g0 = ld_gen_acq();

    uint32_t Ahi[4][4], Alo[4][4];
    preload_A(Whh, blk, w, g, tig, Ahi, Alo);
    if (tid < 16) {
        const int j = (tid >> 2) * 512 + blk * 4 + (tid & 3);
        bias_sh[tid] = __ldg(bih + j) + __ldg(bhh + j);
    }
    for (int idx = tid; idx < 1024; idx += 256) {
        const int row = idx >> 9, hh = idx & 511;
        w2sh[idx] = __ldg(W2w + (size_t)(2 * blk + row) * H_ + hh);
    }
    if (tid < 2) w2bs[tid] = __ldg(W2b + 2 * blk + tid);
    float cc[4] = {0.f, 0.f, 0.f, 0.f};
    if (tid < 64) {
        float hv[4];
#pragma unroll
        for (int cell = 0; cell < 4; cell++) {
            float x = __ldg(h0 + (size_t)tid * H_ + blk * 4 + cell);
            d_dhT[0][(blk * 4 + cell) * 64 + tid] = x;
            hv[cell] = x;
            cc[cell] = __ldg(d_enc + (size_t)(L_ - 1) * H_ * B_ + (blk * 4 + cell) * 64 + tid);
        }
        pack_h(d_dBp[0], blk, tid, hv);
    }
    const int wrp = w;
    const int gw = blk * 8 + wrp;
    const int cb = gw & 63, lbase = (gw >> 6) * 32;
    const float4 vta = __ldg((const float4*)vtw + lane);
    const float4 vtb = __ldg((const float4*)vtw + 32 + lane);
    const int pbg = tid & 15, pwl = (tid >> 4) & 1, pks = tid >> 5;

    grid_barrier(g0 + 1);
    const unsigned base = g0 + 1;

    for (int s = 0; s < T_; s++) {
        const int cur = s & 1, nxt = cur ^ 1;

        // ---- A: recurrent gates via mma.sync ----
        {
            stage_frag(d_dBp[cur], smfrag, tid);
            float D[8][4];
#pragma unroll
            for (int nt = 0; nt < 8; nt++)
#pragma unroll
                for (int i = 0; i < 4; i++) D[nt][i] = 0.0f;
            asm volatile("cp.async.wait_group 1;" ::: "memory");
            __syncthreads();
            compute_group(frag, w, lane, 0, Ahi, Alo, D);
            asm volatile("cp.async.wait_group 0;" ::: "memory");
            __syncthreads();
            compute_group(frag, w, lane, 2, Ahi, Alo, D);
            reduce_gates(psum, gsh, D, w, g, tig, tid);
        }
        if (tid < 64) {
            const int b = tid;
            float hv[4];
#pragma unroll
            for (int cell = 0; cell < 4; cell++) {
                float gi = gsh[(0  + cell) * 65 + b] + bias_sh[cell];
                float gf = gsh[(4  + cell) * 65 + b] + bias_sh[4 + cell];
                float gg = gsh[(8  + cell) * 65 + b] + bias_sh[8 + cell];
                float go = gsh[(12 + cell) * 65 + b] + bias_sh[12 + cell];
                cc[cell] = sigf(gf) * cc[cell] + sigf(gi) * tanh_acc(gg);
                float h = sigf(go) * tanh_acc(cc[cell]);
                d_dhT[nxt][(blk * 4 + cell) * 64 + b] = h;
                hv[cell] = h;
            }
            pack_h(d_dBp[nxt], blk, b, hv);
        }
        grid_barrier(base + 3 * s + 1);

        // ---- B: blend2 rows 2*blk, 2*blk+1 (k-split __ldg) ----
        {
            const float4* hp4 = (const float4*)d_dhT[nxt] + pbg;
            const float* wp = w2sh + pwl * 512 + pks * 64;
            float4 acc = make_float4(0.f, 0.f, 0.f, 0.f);
#pragma unroll 8
            for (int k = 0; k < 64; k++) {
                float4 hv = __ldg(hp4 + (size_t)(pks * 64 + k) * 16);
                float  wv = wp[k];
                acc.x = fmaf(wv, hv.x, acc.x); acc.y = fmaf(wv, hv.y, acc.y);
                acc.z = fmaf(wv, hv.z, acc.z); acc.w = fmaf(wv, hv.w, acc.w);
            }
            *(float4*)&psumB[(pks * 2 + pwl) * 64 + pbg * 4] = acc;
        }
        __syncthreads();
        if (tid < 128) {
            const int b = tid & 63, wl = tid >> 6;
            float sacc = w2bs[wl];
#pragma unroll
            for (int ks = 0; ks < 8; ks++) sacc += psumB[(ks * 2 + wl) * 64 + b];
            d_blend2[b * 256 + 2 * blk + wl] = sacc;
        }
        grid_barrier(base + 3 * s + 2);

        // ---- C: scores[b][l] = tanh(blend1 + blend2) . vt ----
        {
            float4 b2a = __ldcg((const float4*)(d_blend2 + cb * 256) + lane);
            float4 b2b = __ldcg((const float4*)(d_blend2 + cb * 256) + 32 + lane);
            for (int li = 0; li < 32; li++) {
                const int l = lbase + li;
                const float4* bp = (const float4*)(d_blend1 + ((size_t)l * 64 + cb) * 256);
                float4 x = __ldg(bp + lane), y = __ldg(bp + 32 + lane);
                float sv = tanh_fast(x.x + b2a.x) * vta.x + tanh_fast(x.y + b2a.y) * vta.y
                         + tanh_fast(x.z + b2a.z) * vta.z + tanh_fast(x.w + b2a.w) * vta.w
                         + tanh_fast(y.x + b2b.x) * vtb.x + tanh_fast(y.y + b2b.y) * vtb.y
                         + tanh_fast(y.z + b2b.z) * vtb.z + tanh_fast(y.w + b2b.w) * vtb.w;
#pragma unroll
                for (int o = 16; o > 0; o >>= 1) sv += __shfl_xor_sync(0xFFFFFFFFu, sv, o);
                if (lane == 0) d_scores[cb * 512 + l] = sv;
            }
        }
        grid_barrier(base + 3 * s + 3);

        // ---- D: log-softmax over l (shuffle reduction), out[l][b][s] ----
        if (blk < 64) {
            float* red = psumB;
            const int b = blk;
            float s0 = __ldcg(d_scores + b * 512 + tid);
            float s1 = __ldcg(d_scores + b * 512 + tid + 256);
            float m = fmaxf(s0, s1);
#pragma unroll
            for (int o = 16; o > 0; o >>= 1) m = fmaxf(m, __shfl_xor_sync(0xFFFFFFFFu, m, o));
            if (lane == 0) red[wrp] = m;
            __syncthreads();
            float mm = red[0];
#pragma unroll
            for (int i = 1; i < 8; i++) mm = fmaxf(mm, red[i]);
            float se = __expf(s0 - mm) + __expf(s1 - mm);
#pragma unroll
            for (int o = 16; o > 0; o >>= 1) se += __shfl_xor_sync(0xFFFFFFFFu, se, o);
            if (lane == 0) red[8 + wrp] = se;
            __syncthreads();
            float tot = red[8];
#pragma unroll
            for (int i = 9; i < 16; i++) tot += red[i];
            const float lse = mm + __logf(tot);
            out[((size_t)tid         * 64 + b) * 64 + s] = s0 - lse;
            out[((size_t)(tid + 256) * 64 + b) * 64 + s] = s1 - lse;
        }
        __syncthreads();
    }
}

extern "C" void kernel_launch(void* const* d_in, const int* in_sizes, int n_in,
                              void* d_out, int out_size) {
    const int*   ids  = (const int*)  d_in[0];
    const float* emb  = (const float*)d_in[1];
    const float* eWih = (const float*)d_in[2];
    const float* eWhh = (const float*)d_in[3];
    const float* ebih = (const float*)d_in[4];
    const float* ebhh = (const float*)d_in[5];
    const float* dWhh = (const float*)d_in[7];
    const float* dbih = (const float*)d_in[8];
    const float* dbhh = (const float*)d_in[9];
    const float* W1w  = (const float*)d_in[10];
    const float* W1b  = (const float*)d_in[11];
    const float* W2w  = (const float*)d_in[12];
    const float* W2b  = (const float*)d_in[13];
    const float* vtw  = (const float*)d_in[14];
    const float* h0   = (const float*)d_in[16];
    float* out = (float*)d_out;

    cudaFuncSetAttribute(k_encoder, cudaFuncAttributeMaxDynamicSharedMemorySize, ENC_SMEM);
    cudaFuncSetAttribute(k_decoder, cudaFuncAttributeMaxDynamicSharedMemorySize, DEC_SMEM);

    dim3 g1(G_ / 64, (V_ + 63) / 64);
    k_embproj<<<g1, 256>>>(emb, eWih, ebih, ebhh);
    k_encoder<<<NB, 256, ENC_SMEM>>>(ids, eWhh);
    k_blend1<<<L_, 256>>>(W1w, W1b);
    k_decoder<<<NB, 256, DEC_SMEM>>>(dWhh, dbih, dbhh, W2w, W2b, vtw, h0, out);
}

// round 14
// speedup vs baseline: 1.0734x; 1.0536x over previous
#include <cuda_runtime.h>
#include <cuda_fp16.h>
#include <cstdint>

#define L_ 512
#define T_ 64
#define H_ 512
#define B_ 64
#define E_ 256
#define W_ 256
#define V_ 10000
#define G_ 2048
#define NB 128

// ---- static scratch ----
__device__ float d_emb_proj[(size_t)V_ * G_];
__device__ float d_enc[(size_t)L_ * H_ * B_];     // [t][h][b] fp32
__device__ float d_blend1[(size_t)L_ * B_ * W_];  // [l][b][w] fp32
__device__ float d_dhT[2][H_ * B_];               // [h][b] fp32 (decoder)
__device__ float d_blend2[B_ * W_];
__device__ float d_scores[B_ * L_];
__device__ unsigned d_count;
__device__ unsigned d_gen;
// packed h B-fragments (single fp16), double buffered
__device__ uint32_t d_eBp[2][16384];
__device__ uint32_t d_dBp[2][16384];
// fp16 copies for embproj GEMM
__device__ __half d_emb16[(size_t)V_ * E_];
__device__ __half d_wih16[(size_t)G_ * E_];

// SMEM maps (bytes) for encoder/decoder
#define SMO_FRAG  0          // 65536
#define SMO_PSUM  65536      // 32768
#define SMO_GSH   98304      // 4160
#define SMO_IDSA  102464
#define SMO_IDSB  102720
#define ENC_SMEM  102976
#define SMO_W2SH  102464
#define SMO_PSUMB 106560
#define SMO_W2BS  110656
#define SMO_BIAS  110664
#define DEC_SMEM  110728

// embproj SMEM map (u32 word indices); row pitch 132 words (264 fp16)
#define EP_PITCH 132
#define EP_A     0
#define EP_B     (128 * EP_PITCH)                 // 16896
#define EP_BIAS  (EP_B + 64 * EP_PITCH)           // 25344 (float words)
#define EP_SMEM  ((EP_BIAS + 64) * 4)             // 101632 bytes

__device__ __forceinline__ float sigf(float x) { return 1.0f / (1.0f + __expf(-x)); }
__device__ __forceinline__ float tanh_acc(float x) {
    float e = __expf(2.0f * x);
    return 1.0f - 2.0f / (e + 1.0f);
}
__device__ __forceinline__ float tanh_fast(float x) {
    float r; asm("tanh.approx.f32 %0, %1;" : "=f"(r) : "f"(x)); return r;
}
__device__ __forceinline__ unsigned short fphi(float x) {
    return __half_as_ushort(__float2half_rn(x));
}
__device__ __forceinline__ float fp2f(unsigned short u) {
    return __half2float(__ushort_as_half(u));
}

__device__ __forceinline__ unsigned ld_gen_acq() {
    unsigned v;
    asm volatile("ld.acquire.gpu.global.u32 %0, [%1];" : "=r"(v) : "l"(&d_gen) : "memory");
    return v;
}
__device__ __forceinline__ void grid_barrier(unsigned target) {
    __syncthreads();
    if (threadIdx.x == 0) {
        unsigned prev;
        asm volatile("atom.add.release.gpu.global.u32 %0, [%1], 1;"
                     : "=r"(prev) : "l"(&d_count) : "memory");
        if (prev + 1 == target * NB) {
            asm volatile("st.release.gpu.global.u32 [%0], %1;"
                         :: "l"(&d_gen), "r"(target) : "memory");
        } else {
            while (ld_gen_acq() < target) { __nanosleep(32); }
        }
    }
    __syncthreads();
}

// D(16x8,f32) += A(16x16 fp16, row) x B(16x8 fp16, col)
__device__ __forceinline__ void mma_fp16(float* d, const uint32_t* a, uint32_t b0, uint32_t b1) {
    asm volatile(
        "mma.sync.aligned.m16n8k16.row.col.f32.f16.f16.f32 "
        "{%0,%1,%2,%3}, {%4,%5,%6,%7}, {%8,%9}, {%0,%1,%2,%3};"
        : "+f"(d[0]), "+f"(d[1]), "+f"(d[2]), "+f"(d[3])
        : "r"(a[0]), "r"(a[1]), "r"(a[2]), "r"(a[3]), "r"(b0), "r"(b1));
}

// Preload W fragments (A operand), fp16 hi/lo. Warp w owns chunks {w, w+8, w+16, w+24}.
__device__ __forceinline__ void preload_A(const float* __restrict__ Whh, int blk,
                                          int w, int g, int tig,
                                          uint32_t Ahi[4][4], uint32_t Alo[4][4]) {
#pragma unroll
    for (int i = 0; i < 4; i++) {
        const int c = w + 8 * i;
#pragma unroll
        for (int half = 0; half < 2; half++) {
            const int k = c * 16 + 2 * tig + half * 8;
#pragma unroll
            for (int rr = 0; rr < 2; rr++) {
                const int r = g + rr * 8;
                const int j = (r >> 2) * 512 + blk * 4 + (r & 3);
                float x0 = __ldg(Whh + (size_t)j * H_ + k);
                float x1 = __ldg(Whh + (size_t)j * H_ + k + 1);
                unsigned short h0 = fphi(x0), h1 = fphi(x1);
                unsigned short l0 = fphi(x0 - fp2f(h0)), l1 = fphi(x1 - fp2f(h1));
                Ahi[i][half * 2 + rr] = (uint32_t)h0 | ((uint32_t)h1 << 16);
                Alo[i][half * 2 + rr] = (uint32_t)l0 | ((uint32_t)l1 << 16);
            }
        }
    }
}

// Stage 64KB packed fragments in 2 commit groups.
__device__ __forceinline__ void stage_frag(const uint32_t* __restrict__ src,
                                           uint32_t smfrag, int tid) {
    const float4* s4 = (const float4*)src;
#pragma unroll
    for (int i = 0; i < 8; i++) {
        int idx = i * 256 + tid;
        asm volatile("cp.async.cg.shared.global [%0], [%1], 16;"
                     :: "r"(smfrag + idx * 16), "l"(s4 + idx));
    }
    asm volatile("cp.async.commit_group;");
#pragma unroll
    for (int i = 8; i < 16; i++) {
        int idx = i * 256 + tid;
        asm volatile("cp.async.cg.shared.global [%0], [%1], 16;"
                     :: "r"(smfrag + idx * 16), "l"(s4 + idx));
    }
    asm volatile("cp.async.commit_group;");
}

// MMA over 2 chunks starting at group i0.
__device__ __forceinline__ void compute_group(const uint32_t* frag, int w, int lane, int i0,
                                              const uint32_t Ahi[4][4], const uint32_t Alo[4][4],
                                              float D[8][4]) {
#pragma unroll
    for (int ii = 0; ii < 2; ii++) {
        const int i = i0 + ii;
        const uint32_t* fb = frag + (w + 8 * i) * 512;
#pragma unroll
        for (int nt = 0; nt < 8; nt++) {
            uint32_t b0 = fb[nt * 64 + lane];
            uint32_t b1 = fb[nt * 64 + 32 + lane];
            mma_fp16(D[nt], Ahi[i], b0, b1);
            mma_fp16(D[nt], Alo[i], b0, b1);
        }
    }
}

// Producer: pack this step's 4 h values as fp16 fragments.
__device__ __forceinline__ void pack_h(uint32_t* __restrict__ dst, int blk, int b,
                                       const float* hv) {
    const int chunk = blk >> 2, q = blk & 3;
    const int reg = (q >= 2) ? 1 : 0;
    const int p0 = q * 2;
    const int tig0 = p0 & 3, tig1 = (p0 + 1) & 3;
    const int lb = (b & 7) * 4;
    unsigned short h[4];
#pragma unroll
    for (int c2 = 0; c2 < 4; c2++) h[c2] = fphi(hv[c2]);
    const uint32_t base = chunk * 512 + (b >> 3) * 64 + reg * 32;
    dst[base + lb + tig0] = (uint32_t)h[0] | ((uint32_t)h[1] << 16);
    dst[base + lb + tig1] = (uint32_t)h[2] | ((uint32_t)h[3] << 16);
}

// Reduce per-warp D partials into gsh[r*65+b].
__device__ __forceinline__ void reduce_gates(float* psum, float* gsh, float D[8][4],
                                             int w, int g, int tig, int tid) {
#pragma unroll
    for (int nt = 0; nt < 8; nt++) {
        *(float2*)&psum[(w * 16 + g) * 64 + nt * 8 + 2 * tig]     = make_float2(D[nt][0], D[nt][1]);
        *(float2*)&psum[(w * 16 + g + 8) * 64 + nt * 8 + 2 * tig] = make_float2(D[nt][2], D[nt][3]);
    }
    __syncthreads();
    const int rr = tid >> 4, b4 = (tid & 15) * 4;
    float4 acc = *(const float4*)&psum[rr * 64 + b4];
#pragma unroll
    for (int w2 = 1; w2 < 8; w2++) {
        float4 v = *(const float4*)&psum[(w2 * 16 + rr) * 64 + b4];
        acc.x += v.x; acc.y += v.y; acc.z += v.z; acc.w += v.w;
    }
    gsh[rr * 65 + b4 + 0] = acc.x;
    gsh[rr * 65 + b4 + 1] = acc.y;
    gsh[rr * 65 + b4 + 2] = acc.z;
    gsh[rr * 65 + b4 + 3] = acc.w;
    __syncthreads();
}

// ============ K0: fp16 conversions for embproj ============
__global__ void __launch_bounds__(256) k_tofp16(
    const float* __restrict__ emb, const float* __restrict__ Wih)
{
    const size_t nE = (size_t)V_ * E_;
    const size_t nW = (size_t)G_ * E_;
    for (size_t i = (size_t)blockIdx.x * 256 + threadIdx.x; i < nE + nW;
         i += (size_t)gridDim.x * 256) {
        if (i < nE) d_emb16[i] = __float2half_rn(emb[i]);
        else        d_wih16[i - nE] = __float2half_rn(Wih[i - nE]);
    }
}

// ============ K1: emb_proj = emb @ Wih^T + bih + bhh (fp16 mma) ============
// grid (32 j-tiles, 79 v-tiles). Block tile: 128 v x 64 j, K = 256.
__global__ void __launch_bounds__(256) k_embproj(
    const float* __restrict__ bih, const float* __restrict__ bhh)
{
    extern __shared__ __align__(16) uint32_t eps[];
    uint32_t* Ash = eps + EP_A;
    uint32_t* Bsh = eps + EP_B;
    float*    bsh = (float*)(eps + EP_BIAS);
    const uint32_t smb = (uint32_t)__cvta_generic_to_shared(eps);

    const int tid = threadIdx.x;
    const int j0 = blockIdx.x * 64, v0 = blockIdx.y * 128;
    const int lane = tid & 31, w = tid >> 5;
    const int g = lane >> 2, tig = lane & 3;

    // stage A (128 rows x 256 fp16, 32 16B-chunks/row, pitch 132 words)
#pragma unroll
    for (int it = 0; it < 16; it++) {
        const int c = it * 256 + tid;
        const int row = c >> 5, ch = c & 31;
        int v = v0 + row;
        unsigned bytes = (v < V_) ? 16u : 0u;
        if (v >= V_) v = 0;
        const __half* src = d_emb16 + (size_t)v * E_ + ch * 8;
        asm volatile("cp.async.cg.shared.global [%0], [%1], 16, %2;"
                     :: "r"(smb + (EP_A + row * EP_PITCH + ch * 4) * 4), "l"(src), "r"(bytes));
    }
    // stage B (64 rows x 256 fp16)
#pragma unroll
    for (int it = 0; it < 8; it++) {
        const int c = it * 256 + tid;
        const int row = c >> 5, ch = c & 31;
        const __half* src = d_wih16 + (size_t)(j0 + row) * E_ + ch * 8;
        asm volatile("cp.async.cg.shared.global [%0], [%1], 16;"
                     :: "r"(smb + (EP_B + row * EP_PITCH + ch * 4) * 4), "l"(src));
    }
    asm volatile("cp.async.commit_group;");
    if (tid < 64) bsh[tid] = __ldg(bih + j0 + tid) + __ldg(bhh + j0 + tid);
    asm volatile("cp.async.wait_group 0;" ::: "memory");
    __syncthreads();

    const int rb = w * 16;
    float D[8][4];
#pragma unroll
    for (int nt = 0; nt < 8; nt++)
#pragma unroll
        for (int i = 0; i < 4; i++) D[nt][i] = 0.0f;

#pragma unroll
    for (int kt = 0; kt < 16; kt++) {
        uint32_t a[4];
        a[0] = Ash[(rb + g)     * EP_PITCH + kt * 8 + tig];
        a[1] = Ash[(rb + g + 8) * EP_PITCH + kt * 8 + tig];
        a[2] = Ash[(rb + g)     * EP_PITCH + kt * 8 + tig + 4];
        a[3] = Ash[(rb + g + 8) * EP_PITCH + kt * 8 + tig + 4];
#pragma unroll
        for (int nt = 0; nt < 8; nt++) {
            uint32_t b0 = Bsh[(nt * 8 + g) * EP_PITCH + kt * 8 + tig];
            uint32_t b1 = Bsh[(nt * 8 + g) * EP_PITCH + kt * 8 + tig + 4];
            mma_fp16(D[nt], a, b0, b1);
        }
    }

    // epilogue: add bias, store
#pragma unroll
    for (int nt = 0; nt < 8; nt++) {
        const int jl = nt * 8 + 2 * tig;
        const float b0 = bsh[jl], b1 = bsh[jl + 1];
        const int v1 = v0 + rb + g, v2 = v1 + 8;
        if (v1 < V_)
            *(float2*)&d_emb_proj[(size_t)v1 * G_ + j0 + jl] =
                make_float2(D[nt][0] + b0, D[nt][1] + b1);
        if (v2 < V_)
            *(float2*)&d_emb_proj[(size_t)v2 * G_ + j0 + jl] =
                make_float2(D[nt][2] + b0, D[nt][3] + b1);
    }
}

// ============ K2: persistent encoder (mma.sync fp16 W-split) ============
__global__ void __launch_bounds__(256, 1) k_encoder(
    const int* __restrict__ ids, const float* __restrict__ Whh)
{
    extern __shared__ __align__(16) char sm[];
    uint32_t* frag = (uint32_t*)(sm + SMO_FRAG);
    float*    psum = (float*)(sm + SMO_PSUM);
    float*    gsh  = (float*)(sm + SMO_GSH);
    int*      idsA = (int*)(sm + SMO_IDSA);
    int*      idsB = (int*)(sm + SMO_IDSB);

    const int tid = threadIdx.x, blk = blockIdx.x;
    const int lane = tid & 31, w = tid >> 5;
    const int g = lane >> 2, tig = lane & 3;
    const uint32_t smfrag = (uint32_t)__cvta_generic_to_shared(frag);
    unsigned g0 = 0;
    if (tid == 0) g0 = ld_gen_acq();

    uint32_t Ahi[4][4], Alo[4][4];
    preload_A(Whh, blk, w, g, tig, Ahi, Alo);
    if (tid < 64) idsA[tid] = __ldg(ids + tid * L_);
    float cc[4] = {0.f, 0.f, 0.f, 0.f};
    __syncthreads();

    for (int t = 0; t < L_; t++) {
        int* cur_ids = (t & 1) ? idsB : idsA;
        int* nxt_ids = (t & 1) ? idsA : idsB;
        if (t > 0) stage_frag(d_eBp[(t - 1) & 1], smfrag, tid);
        float ei[4], ef[4], eg[4], eo[4];
        if (tid < 64) {
            const float4* ep = (const float4*)(d_emb_proj + (size_t)cur_ids[tid] * G_);
            float4 x0 = __ldg(ep + blk);
            float4 x1 = __ldg(ep + 128 + blk);
            float4 x2 = __ldg(ep + 256 + blk);
            float4 x3 = __ldg(ep + 384 + blk);
            ei[0]=x0.x; ei[1]=x0.y; ei[2]=x0.z; ei[3]=x0.w;
            ef[0]=x1.x; ef[1]=x1.y; ef[2]=x1.z; ef[3]=x1.w;
            eg[0]=x2.x; eg[1]=x2.y; eg[2]=x2.z; eg[3]=x2.w;
            eo[0]=x3.x; eo[1]=x3.y; eo[2]=x3.z; eo[3]=x3.w;
            if (t + 1 < L_) nxt_ids[tid] = __ldg(ids + tid * L_ + t + 1);
        }

        if (t > 0) {
            float D[8][4];
#pragma unroll
            for (int nt = 0; nt < 8; nt++)
#pragma unroll
                for (int i = 0; i < 4; i++) D[nt][i] = 0.0f;
            asm volatile("cp.async.wait_group 1;" ::: "memory");
            __syncthreads();
            compute_group(frag, w, lane, 0, Ahi, Alo, D);
            asm volatile("cp.async.wait_group 0;" ::: "memory");
            __syncthreads();
            compute_group(frag, w, lane, 2, Ahi, Alo, D);
            reduce_gates(psum, gsh, D, w, g, tig, tid);
        }

        if (tid < 64) {
            const int b = tid;
            float hv[4];
#pragma unroll
            for (int cell = 0; cell < 4; cell++) {
                float gi = ((t > 0) ? gsh[(0  + cell) * 65 + b] : 0.f) + ei[cell];
                float gf = ((t > 0) ? gsh[(4  + cell) * 65 + b] : 0.f) + ef[cell];
                float gg = ((t > 0) ? gsh[(8  + cell) * 65 + b] : 0.f) + eg[cell];
                float go = ((t > 0) ? gsh[(12 + cell) * 65 + b] : 0.f) + eo[cell];
                cc[cell] = sigf(gf) * cc[cell] + sigf(gi) * tanh_acc(gg);
                float h = sigf(go) * tanh_acc(cc[cell]);
                d_enc[(size_t)t * H_ * B_ + (blk * 4 + cell) * 64 + b] = h;
                hv[cell] = h;
            }
            pack_h(d_eBp[t & 1], blk, b, hv);
        }
        if (t + 1 < L_) grid_barrier(g0 + t + 1);
    }
}

// ============ K3: blend1[l][b][w] = enc[l] @ W1^T + b1 ============
__global__ void __launch_bounds__(256) k_blend1(
    const float* __restrict__ W1w, const float* __restrict__ W1b)
{
    __shared__ __align__(16) float ensh[32 * 64];
    __shared__ float w1sh[32 * 257];
    const int tid = threadIdx.x, l = blockIdx.x;
    float4 acc[16];
#pragma unroll
    for (int g = 0; g < 16; g++) acc[g] = make_float4(0.f,0.f,0.f,0.f);

    for (int ht = 0; ht < 16; ht++) {
        const float4* ep = (const float4*)(d_enc + (size_t)l * H_ * B_ + (size_t)ht * 32 * 64);
        ((float4*)ensh)[tid]       = __ldg(ep + tid);
        ((float4*)ensh)[tid + 256] = __ldg(ep + tid + 256);
#pragma unroll
        for (int rep = 0; rep < 32; rep++) {
            const int lin = rep * 256 + tid;
            const int w = lin >> 5, hh = lin & 31;
            w1sh[hh * 257 + w] = __ldg(W1w + (size_t)w * H_ + ht * 32 + hh);
        }
        __syncthreads();
#pragma unroll
        for (int hh = 0; hh < 32; hh++) {
            const float wv = w1sh[hh * 257 + tid];
            const float4* e4 = (const float4*)(ensh + hh * 64);
#pragma unroll
            for (int g = 0; g < 16; g++) {
                float4 ev = e4[g];
                acc[g].x = fmaf(wv, ev.x, acc[g].x);
                acc[g].y = fmaf(wv, ev.y, acc[g].y);
                acc[g].z = fmaf(wv, ev.z, acc[g].z);
                acc[g].w = fmaf(wv, ev.w, acc[g].w);
            }
        }
        __syncthreads();
    }
    const float bias = __ldg(W1b + tid);
    float* outp = d_blend1 + (size_t)l * B_ * W_ + tid;
#pragma unroll
    for (int g = 0; g < 16; g++) {
        outp[(g*4+0) * W_] = acc[g].x + bias;
        outp[(g*4+1) * W_] = acc[g].y + bias;
        outp[(g*4+2) * W_] = acc[g].z + bias;
        outp[(g*4+3) * W_] = acc[g].w + bias;
    }
}

// ============ K4: persistent decoder ============
__global__ void __launch_bounds__(256, 1) k_decoder(
    const float* __restrict__ Whh, const float* __restrict__ bih,
    const float* __restrict__ bhh, const float* __restrict__ W2w,
    const float* __restrict__ W2b, const float* __restrict__ vtw,
    const float* __restrict__ h0, float* __restrict__ out)
{
    extern __shared__ __align__(16) char sm[];
    uint32_t* frag  = (uint32_t*)(sm + SMO_FRAG);
    float*    psum  = (float*)(sm + SMO_PSUM);
    float*    gsh   = (float*)(sm + SMO_GSH);
    float*    w2sh  = (float*)(sm + SMO_W2SH);
    float*    psumB = (float*)(sm + SMO_PSUMB);
    float*    w2bs  = (float*)(sm + SMO_W2BS);
    float*    bias_sh = (float*)(sm + SMO_BIAS);

    const int tid = threadIdx.x, blk = blockIdx.x;
    const int lane = tid & 31, w = tid >> 5;
    const int g = lane >> 2, tig = lane & 3;
    const uint32_t smfrag = (uint32_t)__cvta_generic_to_shared(frag);
    unsigned g0 = 0;
    if (tid == 0) g0 = ld_gen_acq();

    uint32_t Ahi[4][4], Alo[4][4];
    preload_A(Whh, blk, w, g, tig, Ahi, Alo);
    if (tid < 16) {
        const int j = (tid >> 2) * 512 + blk * 4 + (tid & 3);
        bias_sh[tid] = __ldg(bih + j) + __ldg(bhh + j);
    }
    for (int idx = tid; idx < 1024; idx += 256) {
        const int row = idx >> 9, hh = idx & 511;
        w2sh[idx] = __ldg(W2w + (size_t)(2 * blk + row) * H_ + hh);
    }
    if (tid < 2) w2bs[tid] = __ldg(W2b + 2 * blk + tid);
    float cc[4] = {0.f, 0.f, 0.f, 0.f};
    if (tid < 64) {
        float hv[4];
#pragma unroll
        for (int cell = 0; cell < 4; cell++) {
            float x = __ldg(h0 + (size_t)tid * H_ + blk * 4 + cell);
            d_dhT[0][(blk * 4 + cell) * 64 + tid] = x;
            hv[cell] = x;
            cc[cell] = __ldg(d_enc + (size_t)(L_ - 1) * H_ * B_ + (blk * 4 + cell) * 64 + tid);
        }
        pack_h(d_dBp[0], blk, tid, hv);
    }
    const int wrp = w;
    const int gw = blk * 8 + wrp;
    const int cb = gw & 63, lbase = (gw >> 6) * 32;
    const float4 vta = __ldg((const float4*)vtw + lane);
    const float4 vtb = __ldg((const float4*)vtw + 32 + lane);
    const int pbg = tid & 15, pwl = (tid >> 4) & 1, pks = tid >> 5;

    grid_barrier(g0 + 1);
    const unsigned base = g0 + 1;

    for (int s = 0; s < T_; s++) {
        const int cur = s & 1, nxt = cur ^ 1;

        // ---- A: recurrent gates via mma.sync ----
        {
            stage_frag(d_dBp[cur], smfrag, tid);
            float D[8][4];
#pragma unroll
            for (int nt = 0; nt < 8; nt++)
#pragma unroll
                for (int i = 0; i < 4; i++) D[nt][i] = 0.0f;
            asm volatile("cp.async.wait_group 1;" ::: "memory");
            __syncthreads();
            compute_group(frag, w, lane, 0, Ahi, Alo, D);
            asm volatile("cp.async.wait_group 0;" ::: "memory");
            __syncthreads();
            compute_group(frag, w, lane, 2, Ahi, Alo, D);
            reduce_gates(psum, gsh, D, w, g, tig, tid);
        }
        if (tid < 64) {
            const int b = tid;
            float hv[4];
#pragma unroll
            for (int cell = 0; cell < 4; cell++) {
                float gi = gsh[(0  + cell) * 65 + b] + bias_sh[cell];
                float gf = gsh[(4  + cell) * 65 + b] + bias_sh[4 + cell];
                float gg = gsh[(8  + cell) * 65 + b] + bias_sh[8 + cell];
                float go = gsh[(12 + cell) * 65 + b] + bias_sh[12 + cell];
                cc[cell] = sigf(gf) * cc[cell] + sigf(gi) * tanh_acc(gg);
                float h = sigf(go) * tanh_acc(cc[cell]);
                d_dhT[nxt][(blk * 4 + cell) * 64 + b] = h;
                hv[cell] = h;
            }
            pack_h(d_dBp[nxt], blk, b, hv);
        }
        grid_barrier(base + 3 * s + 1);

        // ---- B: blend2 rows 2*blk, 2*blk+1 (k-split __ldg) ----
        {
            const float4* hp4 = (const float4*)d_dhT[nxt] + pbg;
            const float* wp = w2sh + pwl * 512 + pks * 64;
            float4 acc = make_float4(0.f, 0.f, 0.f, 0.f);
#pragma unroll 8
            for (int k = 0; k < 64; k++) {
                float4 hv = __ldg(hp4 + (size_t)(pks * 64 + k) * 16);
                float  wv = wp[k];
                acc.x = fmaf(wv, hv.x, acc.x); acc.y = fmaf(wv, hv.y, acc.y);
                acc.z = fmaf(wv, hv.z, acc.z); acc.w = fmaf(wv, hv.w, acc.w);
            }
            *(float4*)&psumB[(pks * 2 + pwl) * 64 + pbg * 4] = acc;
        }
        __syncthreads();
        if (tid < 128) {
            const int b = tid & 63, wl = tid >> 6;
            float sacc = w2bs[wl];
#pragma unroll
            for (int ks = 0; ks < 8; ks++) sacc += psumB[(ks * 2 + wl) * 64 + b];
            d_blend2[b * 256 + 2 * blk + wl] = sacc;
        }
        grid_barrier(base + 3 * s + 2);

        // ---- C: scores[b][l] = tanh(blend1 + blend2) . vt ----
        {
            float4 b2a = __ldcg((const float4*)(d_blend2 + cb * 256) + lane);
            float4 b2b = __ldcg((const float4*)(d_blend2 + cb * 256) + 32 + lane);
            for (int li = 0; li < 32; li++) {
                const int l = lbase + li;
                const float4* bp = (const float4*)(d_blend1 + ((size_t)l * 64 + cb) * 256);
                float4 x = __ldg(bp + lane), y = __ldg(bp + 32 + lane);
                float sv = tanh_fast(x.x + b2a.x) * vta.x + tanh_fast(x.y + b2a.y) * vta.y
                         + tanh_fast(x.z + b2a.z) * vta.z + tanh_fast(x.w + b2a.w) * vta.w
                         + tanh_fast(y.x + b2b.x) * vtb.x + tanh_fast(y.y + b2b.y) * vtb.y
                         + tanh_fast(y.z + b2b.z) * vtb.z + tanh_fast(y.w + b2b.w) * vtb.w;
#pragma unroll
                for (int o = 16; o > 0; o >>= 1) sv += __shfl_xor_sync(0xFFFFFFFFu, sv, o);
                if (lane == 0) d_scores[cb * 512 + l] = sv;
            }
        }
        grid_barrier(base + 3 * s + 3);

        // ---- D: log-softmax over l (shuffle reduction), out[l][b][s] ----
        if (blk < 64) {
            float* red = psumB;
            const int b = blk;
            float s0 = __ldcg(d_scores + b * 512 + tid);
            float s1 = __ldcg(d_scores + b * 512 + tid + 256);
            float m = fmaxf(s0, s1);
#pragma unroll
            for (int o = 16; o > 0; o >>= 1) m = fmaxf(m, __shfl_xor_sync(0xFFFFFFFFu, m, o));
            if (lane == 0) red[wrp] = m;
            __syncthreads();
            float mm = red[0];
#pragma unroll
            for (int i = 1; i < 8; i++) mm = fmaxf(mm, red[i]);
            float se = __expf(s0 - mm) + __expf(s1 - mm);
#pragma unroll
            for (int o = 16; o > 0; o >>= 1) se += __shfl_xor_sync(0xFFFFFFFFu, se, o);
            if (lane == 0) red[8 + wrp] = se;
            __syncthreads();
            float tot = red[8];
#pragma unroll
            for (int i = 9; i < 16; i++) tot += red[i];
            const float lse = mm + __logf(tot);
            out[((size_t)tid         * 64 + b) * 64 + s] = s0 - lse;
            out[((size_t)(tid + 256) * 64 + b) * 64 + s] = s1 - lse;
        }
        __syncthreads();
    }
}

extern "C" void kernel_launch(void* const* d_in, const int* in_sizes, int n_in,
                              void* d_out, int out_size) {
    const int*   ids  = (const int*)  d_in[0];
    const float* emb  = (const float*)d_in[1];
    const float* eWih = (const float*)d_in[2];
    const float* eWhh = (const float*)d_in[3];
    const float* ebih = (const float*)d_in[4];
    const float* ebhh = (const float*)d_in[5];
    const float* dWhh = (const float*)d_in[7];
    const float* dbih = (const float*)d_in[8];
    const float* dbhh = (const float*)d_in[9];
    const float* W1w  = (const float*)d_in[10];
    const float* W1b  = (const float*)d_in[11];
    const float* W2w  = (const float*)d_in[12];
    const float* W2b  = (const float*)d_in[13];
    const float* vtw  = (const float*)d_in[14];
    const float* h0   = (const float*)d_in[16];
    float* out = (float*)d_out;

    cudaFuncSetAttribute(k_embproj, cudaFuncAttributeMaxDynamicSharedMemorySize, EP_SMEM);
    cudaFuncSetAttribute(k_encoder, cudaFuncAttributeMaxDynamicSharedMemorySize, ENC_SMEM);
    cudaFuncSetAttribute(k_decoder, cudaFuncAttributeMaxDynamicSharedMemorySize, DEC_SMEM);

    k_tofp16<<<1024, 256>>>(emb, eWih);
    dim3 g1(G_ / 64, (V_ + 127) / 128);
    k_embproj<<<g1, 256, EP_SMEM>>>(ebih, ebhh);
    k_encoder<<<NB, 256, ENC_SMEM>>>(ids, eWhh);
    k_blend1<<<L_, 256>>>(W1w, W1b);
    k_decoder<<<NB, 256, DEC_SMEM>>>(dWhh, dbih, dbhh, W2w, W2b, vtw, h0, out);
}

// round 16
// speedup vs baseline: 1.1790x; 1.0984x over previous
#include <cuda_runtime.h>
#include <cuda_fp16.h>
#include <cstdint>

#define L_ 512
#define T_ 64
#define H_ 512
#define B_ 64
#define E_ 256
#define W_ 256
#define V_ 10000
#define G_ 2048
#define NB 128

// ---- static scratch ----
__device__ float d_emb_proj[(size_t)V_ * G_];
__device__ float d_enc[(size_t)L_ * H_ * B_];     // [t][h][b] fp32 (c0 init)
__device__ __half d_enc16[(size_t)L_ * B_ * H_];  // [(l*64+b)][h] fp16 (blend1 A)
__device__ float d_blend1[(size_t)L_ * B_ * W_];  // [l][b][w] fp32
__device__ float d_dhT[2][H_ * B_];               // [h][b] fp32 (decoder)
__device__ float d_blend2[B_ * W_];
__device__ float d_scores[B_ * L_];
__device__ unsigned d_count;
__device__ unsigned d_gen;
// packed h B-fragments (single fp16), double buffered
__device__ uint32_t d_eBp[2][16384];
__device__ uint32_t d_dBp[2][16384];
// fp16 weight/input copies for mma GEMMs
__device__ __half d_emb16[(size_t)V_ * E_];
__device__ __half d_wih16[(size_t)G_ * E_];
__device__ __half d_w1_16[(size_t)W_ * H_];

// SMEM maps (bytes) for encoder/decoder
#define SMO_FRAG  0          // 65536
#define SMO_PSUM  65536      // 32768
#define SMO_GSH   98304      // 4160
#define SMO_IDSA  102464
#define SMO_IDSB  102720
#define ENC_SMEM  102976
#define SMO_W2SH  102464
#define SMO_PSUMB 106560
#define SMO_W2BS  110656
#define SMO_BIAS  110664
#define DEC_SMEM  110728

// embproj/blend1 SMEM map (u32 word indices); row pitch 132 words (264 fp16)
#define EP_PITCH 132
#define EP_A     0
#define EP_B     (128 * EP_PITCH)
#define EP_BIAS  (EP_B + 64 * EP_PITCH)
#define EP_SMEM  ((EP_BIAS + 64) * 4)

__device__ __forceinline__ float sigf(float x) { return 1.0f / (1.0f + __expf(-x)); }
__device__ __forceinline__ float tanh_acc(float x) {
    float e = __expf(2.0f * x);
    return 1.0f - 2.0f / (e + 1.0f);
}
__device__ __forceinline__ float tanh_fast(float x) {
    float r; asm("tanh.approx.f32 %0, %1;" : "=f"(r) : "f"(x)); return r;
}
__device__ __forceinline__ unsigned short fphi(float x) {
    return __half_as_ushort(__float2half_rn(x));
}
__device__ __forceinline__ float fp2f(unsigned short u) {
    return __half2float(__ushort_as_half(u));
}

__device__ __forceinline__ unsigned ld_gen_acq() {
    unsigned v;
    asm volatile("ld.acquire.gpu.global.u32 %0, [%1];" : "=r"(v) : "l"(&d_gen) : "memory");
    return v;
}
__device__ __forceinline__ void grid_barrier(unsigned target) {
    __syncthreads();
    if (threadIdx.x == 0) {
        unsigned prev;
        asm volatile("atom.add.release.gpu.global.u32 %0, [%1], 1;"
                     : "=r"(prev) : "l"(&d_count) : "memory");
        if (prev + 1 == target * NB) {
            asm volatile("st.release.gpu.global.u32 [%0], %1;"
                         :: "l"(&d_gen), "r"(target) : "memory");
        } else {
            while (ld_gen_acq() < target) { __nanosleep(32); }
        }
    }
    __syncthreads();
}

// D(16x8,f32) += A(16x16 fp16, row) x B(16x8 fp16, col)
__device__ __forceinline__ void mma_fp16(float* d, const uint32_t* a, uint32_t b0, uint32_t b1) {
    asm volatile(
        "mma.sync.aligned.m16n8k16.row.col.f32.f16.f16.f32 "
        "{%0,%1,%2,%3}, {%4,%5,%6,%7}, {%8,%9}, {%0,%1,%2,%3};"
        : "+f"(d[0]), "+f"(d[1]), "+f"(d[2]), "+f"(d[3])
        : "r"(a[0]), "r"(a[1]), "r"(a[2]), "r"(a[3]), "r"(b0), "r"(b1));
}

// Preload W fragments (A operand), fp16 hi/lo. Warp w owns chunks {w, w+8, w+16, w+24}.
__device__ __forceinline__ void preload_A(const float* __restrict__ Whh, int blk,
                                          int w, int g, int tig,
                                          uint32_t Ahi[4][4], uint32_t Alo[4][4]) {
#pragma unroll
    for (int i = 0; i < 4; i++) {
        const int c = w + 8 * i;
#pragma unroll
        for (int half = 0; half < 2; half++) {
            const int k = c * 16 + 2 * tig + half * 8;
#pragma unroll
            for (int rr = 0; rr < 2; rr++) {
                const int r = g + rr * 8;
                const int j = (r >> 2) * 512 + blk * 4 + (r & 3);
                float x0 = __ldg(Whh + (size_t)j * H_ + k);
                float x1 = __ldg(Whh + (size_t)j * H_ + k + 1);
                unsigned short h0 = fphi(x0), h1 = fphi(x1);
                unsigned short l0 = fphi(x0 - fp2f(h0)), l1 = fphi(x1 - fp2f(h1));
                Ahi[i][half * 2 + rr] = (uint32_t)h0 | ((uint32_t)h1 << 16);
                Alo[i][half * 2 + rr] = (uint32_t)l0 | ((uint32_t)l1 << 16);
            }
        }
    }
}

// Stage 64KB packed fragments in 2 commit groups.
__device__ __forceinline__ void stage_frag(const uint32_t* __restrict__ src,
                                           uint32_t smfrag, int tid) {
    const float4* s4 = (const float4*)src;
#pragma unroll
    for (int i = 0; i < 8; i++) {
        int idx = i * 256 + tid;
        asm volatile("cp.async.cg.shared.global [%0], [%1], 16;"
                     :: "r"(smfrag + idx * 16), "l"(s4 + idx));
    }
    asm volatile("cp.async.commit_group;");
#pragma unroll
    for (int i = 8; i < 16; i++) {
        int idx = i * 256 + tid;
        asm volatile("cp.async.cg.shared.global [%0], [%1], 16;"
                     :: "r"(smfrag + idx * 16), "l"(s4 + idx));
    }
    asm volatile("cp.async.commit_group;");
}

// MMA over 2 chunks starting at group i0.
__device__ __forceinline__ void compute_group(const uint32_t* frag, int w, int lane, int i0,
                                              const uint32_t Ahi[4][4], const uint32_t Alo[4][4],
                                              float D[8][4]) {
#pragma unroll
    for (int ii = 0; ii < 2; ii++) {
        const int i = i0 + ii;
        const uint32_t* fb = frag + (w + 8 * i) * 512;
#pragma unroll
        for (int nt = 0; nt < 8; nt++) {
            uint32_t b0 = fb[nt * 64 + lane];
            uint32_t b1 = fb[nt * 64 + 32 + lane];
            mma_fp16(D[nt], Ahi[i], b0, b1);
            mma_fp16(D[nt], Alo[i], b0, b1);
        }
    }
}

// Producer: pack this step's 4 h values as fp16 fragments.
__device__ __forceinline__ void pack_h(uint32_t* __restrict__ dst, int blk, int b,
                                       const float* hv) {
    const int chunk = blk >> 2, q = blk & 3;
    const int reg = (q >= 2) ? 1 : 0;
    const int p0 = q * 2;
    const int tig0 = p0 & 3, tig1 = (p0 + 1) & 3;
    const int lb = (b & 7) * 4;
    unsigned short h[4];
#pragma unroll
    for (int c2 = 0; c2 < 4; c2++) h[c2] = fphi(hv[c2]);
    const uint32_t base = chunk * 512 + (b >> 3) * 64 + reg * 32;
    dst[base + lb + tig0] = (uint32_t)h[0] | ((uint32_t)h[1] << 16);
    dst[base + lb + tig1] = (uint32_t)h[2] | ((uint32_t)h[3] << 16);
}

// Reduce per-warp D partials into gsh[r*65+b].
__device__ __forceinline__ void reduce_gates(float* psum, float* gsh, float D[8][4],
                                             int w, int g, int tig, int tid) {
#pragma unroll
    for (int nt = 0; nt < 8; nt++) {
        *(float2*)&psum[(w * 16 + g) * 64 + nt * 8 + 2 * tig]     = make_float2(D[nt][0], D[nt][1]);
        *(float2*)&psum[(w * 16 + g + 8) * 64 + nt * 8 + 2 * tig] = make_float2(D[nt][2], D[nt][3]);
    }
    __syncthreads();
    const int rr = tid >> 4, b4 = (tid & 15) * 4;
    float4 acc = *(const float4*)&psum[rr * 64 + b4];
#pragma unroll
    for (int w2 = 1; w2 < 8; w2++) {
        float4 v = *(const float4*)&psum[(w2 * 16 + rr) * 64 + b4];
        acc.x += v.x; acc.y += v.y; acc.z += v.z; acc.w += v.w;
    }
    gsh[rr * 65 + b4 + 0] = acc.x;
    gsh[rr * 65 + b4 + 1] = acc.y;
    gsh[rr * 65 + b4 + 2] = acc.z;
    gsh[rr * 65 + b4 + 3] = acc.w;
    __syncthreads();
}

// ============ K0: fp16 conversions ============
__global__ void __launch_bounds__(256) k_tofp16(
    const float* __restrict__ emb, const float* __restrict__ Wih,
    const float* __restrict__ W1w)
{
    const size_t nE = (size_t)V_ * E_;
    const size_t nW = (size_t)G_ * E_;
    const size_t nW1 = (size_t)W_ * H_;
    for (size_t i = (size_t)blockIdx.x * 256 + threadIdx.x; i < nE + nW + nW1;
         i += (size_t)gridDim.x * 256) {
        if (i < nE)            d_emb16[i] = __float2half_rn(emb[i]);
        else if (i < nE + nW)  d_wih16[i - nE] = __float2half_rn(Wih[i - nE]);
        else                   d_w1_16[i - nE - nW] = __float2half_rn(W1w[i - nE - nW]);
    }
}

// ============ K1: emb_proj = emb @ Wih^T + bih + bhh (fp16 mma) ============
__global__ void __launch_bounds__(256) k_embproj(
    const float* __restrict__ bih, const float* __restrict__ bhh)
{
    extern __shared__ __align__(16) uint32_t eps[];
    uint32_t* Ash = eps + EP_A;
    uint32_t* Bsh = eps + EP_B;
    float*    bsh = (float*)(eps + EP_BIAS);
    const uint32_t smb = (uint32_t)__cvta_generic_to_shared(eps);

    const int tid = threadIdx.x;
    const int j0 = blockIdx.x * 64, v0 = blockIdx.y * 128;
    const int lane = tid & 31, w = tid >> 5;
    const int g = lane >> 2, tig = lane & 3;

#pragma unroll
    for (int it = 0; it < 16; it++) {
        const int c = it * 256 + tid;
        const int row = c >> 5, ch = c & 31;
        int v = v0 + row;
        unsigned bytes = (v < V_) ? 16u : 0u;
        if (v >= V_) v = 0;
        const __half* src = d_emb16 + (size_t)v * E_ + ch * 8;
        asm volatile("cp.async.cg.shared.global [%0], [%1], 16, %2;"
                     :: "r"(smb + (EP_A + row * EP_PITCH + ch * 4) * 4), "l"(src), "r"(bytes));
    }
#pragma unroll
    for (int it = 0; it < 8; it++) {
        const int c = it * 256 + tid;
        const int row = c >> 5, ch = c & 31;
        const __half* src = d_wih16 + (size_t)(j0 + row) * E_ + ch * 8;
        asm volatile("cp.async.cg.shared.global [%0], [%1], 16;"
                     :: "r"(smb + (EP_B + row * EP_PITCH + ch * 4) * 4), "l"(src));
    }
    asm volatile("cp.async.commit_group;");
    if (tid < 64) bsh[tid] = __ldg(bih + j0 + tid) + __ldg(bhh + j0 + tid);
    asm volatile("cp.async.wait_group 0;" ::: "memory");
    __syncthreads();

    const int rb = w * 16;
    float D[8][4];
#pragma unroll
    for (int nt = 0; nt < 8; nt++)
#pragma unroll
        for (int i = 0; i < 4; i++) D[nt][i] = 0.0f;

#pragma unroll
    for (int kt = 0; kt < 16; kt++) {
        uint32_t a[4];
        a[0] = Ash[(rb + g)     * EP_PITCH + kt * 8 + tig];
        a[1] = Ash[(rb + g + 8) * EP_PITCH + kt * 8 + tig];
        a[2] = Ash[(rb + g)     * EP_PITCH + kt * 8 + tig + 4];
        a[3] = Ash[(rb + g + 8) * EP_PITCH + kt * 8 + tig + 4];
#pragma unroll
        for (int nt = 0; nt < 8; nt++) {
            uint32_t b0 = Bsh[(nt * 8 + g) * EP_PITCH + kt * 8 + tig];
            uint32_t b1 = Bsh[(nt * 8 + g) * EP_PITCH + kt * 8 + tig + 4];
            mma_fp16(D[nt], a, b0, b1);
        }
    }

#pragma unroll
    for (int nt = 0; nt < 8; nt++) {
        const int jl = nt * 8 + 2 * tig;
        const float b0 = bsh[jl], b1 = bsh[jl + 1];
        const int v1 = v0 + rb + g, v2 = v1 + 8;
        if (v1 < V_)
            *(float2*)&d_emb_proj[(size_t)v1 * G_ + j0 + jl] =
                make_float2(D[nt][0] + b0, D[nt][1] + b1);
        if (v2 < V_)
            *(float2*)&d_emb_proj[(size_t)v2 * G_ + j0 + jl] =
                make_float2(D[nt][2] + b0, D[nt][3] + b1);
    }
}

// ============ K2: persistent encoder (mma.sync fp16 W-split) ============
__global__ void __launch_bounds__(256, 1) k_encoder(
    const int* __restrict__ ids, const float* __restrict__ Whh)
{
    extern __shared__ __align__(16) char sm[];
    uint32_t* frag = (uint32_t*)(sm + SMO_FRAG);
    float*    psum = (float*)(sm + SMO_PSUM);
    float*    gsh  = (float*)(sm + SMO_GSH);
    int*      idsA = (int*)(sm + SMO_IDSA);
    int*      idsB = (int*)(sm + SMO_IDSB);

    const int tid = threadIdx.x, blk = blockIdx.x;
    const int lane = tid & 31, w = tid >> 5;
    const int g = lane >> 2, tig = lane & 3;
    const uint32_t smfrag = (uint32_t)__cvta_generic_to_shared(frag);
    unsigned g0 = 0;
    if (tid == 0) g0 = ld_gen_acq();

    uint32_t Ahi[4][4], Alo[4][4];
    preload_A(Whh, blk, w, g, tig, Ahi, Alo);
    if (tid < 64) idsA[tid] = __ldg(ids + tid * L_);
    float cc[4] = {0.f, 0.f, 0.f, 0.f};
    __syncthreads();

    for (int t = 0; t < L_; t++) {
        int* cur_ids = (t & 1) ? idsB : idsA;
        int* nxt_ids = (t & 1) ? idsA : idsB;
        if (t > 0) stage_frag(d_eBp[(t - 1) & 1], smfrag, tid);
        float ei[4], ef[4], eg[4], eo[4];
        if (tid < 64) {
            const float4* ep = (const float4*)(d_emb_proj + (size_t)cur_ids[tid] * G_);
            float4 x0 = __ldg(ep + blk);
            float4 x1 = __ldg(ep + 128 + blk);
            float4 x2 = __ldg(ep + 256 + blk);
            float4 x3 = __ldg(ep + 384 + blk);
            ei[0]=x0.x; ei[1]=x0.y; ei[2]=x0.z; ei[3]=x0.w;
            ef[0]=x1.x; ef[1]=x1.y; ef[2]=x1.z; ef[3]=x1.w;
            eg[0]=x2.x; eg[1]=x2.y; eg[2]=x2.z; eg[3]=x2.w;
            eo[0]=x3.x; eo[1]=x3.y; eo[2]=x3.z; eo[3]=x3.w;
            if (t + 1 < L_) nxt_ids[tid] = __ldg(ids + tid * L_ + t + 1);
        }

        if (t > 0) {
            float D[8][4];
#pragma unroll
            for (int nt = 0; nt < 8; nt++)
#pragma unroll
                for (int i = 0; i < 4; i++) D[nt][i] = 0.0f;
            asm volatile("cp.async.wait_group 1;" ::: "memory");
            __syncthreads();
            compute_group(frag, w, lane, 0, Ahi, Alo, D);
            asm volatile("cp.async.wait_group 0;" ::: "memory");
            __syncthreads();
            compute_group(frag, w, lane, 2, Ahi, Alo, D);
            reduce_gates(psum, gsh, D, w, g, tig, tid);
        }

        if (tid < 64) {
            const int b = tid;
            float hv[4];
            unsigned long long pk = 0;
#pragma unroll
            for (int cell = 0; cell < 4; cell++) {
                float gi = ((t > 0) ? gsh[(0  + cell) * 65 + b] : 0.f) + ei[cell];
                float gf = ((t > 0) ? gsh[(4  + cell) * 65 + b] : 0.f) + ef[cell];
                float gg = ((t > 0) ? gsh[(8  + cell) * 65 + b] : 0.f) + eg[cell];
                float go = ((t > 0) ? gsh[(12 + cell) * 65 + b] : 0.f) + eo[cell];
                cc[cell] = sigf(gf) * cc[cell] + sigf(gi) * tanh_acc(gg);
                float h = sigf(go) * tanh_acc(cc[cell]);
                d_enc[(size_t)t * H_ * B_ + (blk * 4 + cell) * 64 + b] = h;
                hv[cell] = h;
                pk |= (unsigned long long)fphi(h) << (cell * 16);
            }
            // fp16 copy in [(l*64+b)][h] layout for blend1 mma
            *(unsigned long long*)(d_enc16 + ((size_t)t * 64 + b) * 512 + blk * 4) = pk;
            pack_h(d_eBp[t & 1], blk, b, hv);
        }
        if (t + 1 < L_) grid_barrier(g0 + t + 1);
    }
}

// ============ K3: blend1 via fp16 mma. Grid (4 w-tiles, 256 row-tiles). ============
// Block tile: 128 rows ((l,b) pairs) x 64 w, K = 512 in 2 staged passes of 256.
__global__ void __launch_bounds__(256) k_blend1(const float* __restrict__ W1b)
{
    extern __shared__ __align__(16) uint32_t eps[];
    uint32_t* Ash = eps + EP_A;
    uint32_t* Bsh = eps + EP_B;
    float*    bsh = (float*)(eps + EP_BIAS);
    const uint32_t smb = (uint32_t)__cvta_generic_to_shared(eps);

    const int tid = threadIdx.x;
    const int j0 = blockIdx.x * 64;
    const int v0 = blockIdx.y * 128;       // row base in [0, 32768)
    const int lane = tid & 31, w = tid >> 5;
    const int g = lane >> 2, tig = lane & 3;
    const int rb = w * 16;

    if (tid < 64) bsh[tid] = __ldg(W1b + j0 + tid);

    float D[8][4];
#pragma unroll
    for (int nt = 0; nt < 8; nt++)
#pragma unroll
        for (int i = 0; i < 4; i++) D[nt][i] = 0.0f;

#pragma unroll
    for (int p = 0; p < 2; p++) {
        const int k0 = p * 256;
        // stage A (128 rows x 256 fp16 of this k-chunk)
#pragma unroll
        for (int it = 0; it < 16; it++) {
            const int c = it * 256 + tid;
            const int row = c >> 5, ch = c & 31;
            const __half* src = d_enc16 + (size_t)(v0 + row) * H_ + k0 + ch * 8;
            asm volatile("cp.async.cg.shared.global [%0], [%1], 16;"
                         :: "r"(smb + (EP_A + row * EP_PITCH + ch * 4) * 4), "l"(src));
        }
        // stage B (64 w-rows x 256 fp16)
#pragma unroll
        for (int it = 0; it < 8; it++) {
            const int c = it * 256 + tid;
            const int row = c >> 5, ch = c & 31;
            const __half* src = d_w1_16 + (size_t)(j0 + row) * H_ + k0 + ch * 8;
            asm volatile("cp.async.cg.shared.global [%0], [%1], 16;"
                         :: "r"(smb + (EP_B + row * EP_PITCH + ch * 4) * 4), "l"(src));
        }
        asm volatile("cp.async.commit_group;");
        asm volatile("cp.async.wait_group 0;" ::: "memory");
        __syncthreads();

#pragma unroll
        for (int kt = 0; kt < 16; kt++) {
            uint32_t a[4];
            a[0] = Ash[(rb + g)     * EP_PITCH + kt * 8 + tig];
            a[1] = Ash[(rb + g + 8) * EP_PITCH + kt * 8 + tig];
            a[2] = Ash[(rb + g)     * EP_PITCH + kt * 8 + tig + 4];
            a[3] = Ash[(rb + g + 8) * EP_PITCH + kt * 8 + tig + 4];
#pragma unroll
            for (int nt = 0; nt < 8; nt++) {
                uint32_t b0 = Bsh[(nt * 8 + g) * EP_PITCH + kt * 8 + tig];
                uint32_t b1 = Bsh[(nt * 8 + g) * EP_PITCH + kt * 8 + tig + 4];
                mma_fp16(D[nt], a, b0, b1);
            }
        }
        __syncthreads();
    }

#pragma unroll
    for (int nt = 0; nt < 8; nt++) {
        const int jl = nt * 8 + 2 * tig;
        const float b0 = bsh[jl], b1 = bsh[jl + 1];
        const int r1 = v0 + rb + g, r2 = r1 + 8;
        *(float2*)&d_blend1[(size_t)r1 * W_ + j0 + jl] =
            make_float2(D[nt][0] + b0, D[nt][1] + b1);
        *(float2*)&d_blend1[(size_t)r2 * W_ + j0 + jl] =
            make_float2(D[nt][2] + b0, D[nt][3] + b1);
    }
}

// ============ K4: persistent decoder ============
__global__ void __launch_bounds__(256, 1) k_decoder(
    const float* __restrict__ Whh, const float* __restrict__ bih,
    const float* __restrict__ bhh, const float* __restrict__ W2w,
    const float* __restrict__ W2b, const float* __restrict__ vtw,
    const float* __restrict__ h0, float* __restrict__ out)
{
    extern __shared__ __align__(16) char sm[];
    uint32_t* frag  = (uint32_t*)(sm + SMO_FRAG);
    float*    psum  = (float*)(sm + SMO_PSUM);
    float*    gsh   = (float*)(sm + SMO_GSH);
    float*    w2sh  = (float*)(sm + SMO_W2SH);
    float*    psumB = (float*)(sm + SMO_PSUMB);
    float*    w2bs  = (float*)(sm + SMO_W2BS);
    float*    bias_sh = (float*)(sm + SMO_BIAS);

    const int tid = threadIdx.x, blk = blockIdx.x;
    const int lane = tid & 31, w = tid >> 5;
    const int g = lane >> 2, tig = lane & 3;
    const uint32_t smfrag = (uint32_t)__cvta_generic_to_shared(frag);
    unsigned g0 = 0;
    if (tid == 0) g0 = ld_gen_acq();

    uint32_t Ahi[4][4], Alo[4][4];
    preload_A(Whh, blk, w, g, tig, Ahi, Alo);
    if (tid < 16) {
        const int j = (tid >> 2) * 512 + blk * 4 + (tid & 3);
        bias_sh[tid] = __ldg(bih + j) + __ldg(bhh + j);
    }
    for (int idx = tid; idx < 1024; idx += 256) {
        const int row = idx >> 9, hh = idx & 511;
        w2sh[idx] = __ldg(W2w + (size_t)(2 * blk + row) * H_ + hh);
    }
    if (tid < 2) w2bs[tid] = __ldg(W2b + 2 * blk + tid);
    float cc[4] = {0.f, 0.f, 0.f, 0.f};
    if (tid < 64) {
        float hv[4];
#pragma unroll
        for (int cell = 0; cell < 4; cell++) {
            float x = __ldg(h0 + (size_t)tid * H_ + blk * 4 + cell);
            d_dhT[0][(blk * 4 + cell) * 64 + tid] = x;
            hv[cell] = x;
            cc[cell] = __ldg(d_enc + (size_t)(L_ - 1) * H_ * B_ + (blk * 4 + cell) * 64 + tid);
        }
        pack_h(d_dBp[0], blk, tid, hv);
    }
    const int wrp = w;
    const int gw = blk * 8 + wrp;
    const int cb = gw & 63, lbase = (gw >> 6) * 32;
    const float4 vta = __ldg((const float4*)vtw + lane);
    const float4 vtb = __ldg((const float4*)vtw + 32 + lane);
    const int pbg = tid & 15, pwl = (tid >> 4) & 1, pks = tid >> 5;

    grid_barrier(g0 + 1);
    const unsigned base = g0 + 1;

    for (int s = 0; s < T_; s++) {
        const int cur = s & 1, nxt = cur ^ 1;

        // ---- A: recurrent gates via mma.sync ----
        {
            stage_frag(d_dBp[cur], smfrag, tid);
            float D[8][4];
#pragma unroll
            for (int nt = 0; nt < 8; nt++)
#pragma unroll
                for (int i = 0; i < 4; i++) D[nt][i] = 0.0f;
            asm volatile("cp.async.wait_group 1;" ::: "memory");
            __syncthreads();
            compute_group(frag, w, lane, 0, Ahi, Alo, D);
            asm volatile("cp.async.wait_group 0;" ::: "memory");
            __syncthreads();
            compute_group(frag, w, lane, 2, Ahi, Alo, D);
            reduce_gates(psum, gsh, D, w, g, tig, tid);
        }
        if (tid < 64) {
            const int b = tid;
            float hv[4];
#pragma unroll
            for (int cell = 0; cell < 4; cell++) {
                float gi = gsh[(0  + cell) * 65 + b] + bias_sh[cell];
                float gf = gsh[(4  + cell) * 65 + b] + bias_sh[4 + cell];
                float gg = gsh[(8  + cell) * 65 + b] + bias_sh[8 + cell];
                float go = gsh[(12 + cell) * 65 + b] + bias_sh[12 + cell];
                cc[cell] = sigf(gf) * cc[cell] + sigf(gi) * tanh_acc(gg);
                float h = sigf(go) * tanh_acc(cc[cell]);
                d_dhT[nxt][(blk * 4 + cell) * 64 + b] = h;
                hv[cell] = h;
            }
            pack_h(d_dBp[nxt], blk, b, hv);
        }
        grid_barrier(base + 3 * s + 1);

        // ---- B: blend2 rows 2*blk, 2*blk+1 (k-split __ldg) ----
        {
            const float4* hp4 = (const float4*)d_dhT[nxt] + pbg;
            const float* wp = w2sh + pwl * 512 + pks * 64;
            float4 acc = make_float4(0.f, 0.f, 0.f, 0.f);
#pragma unroll 8
            for (int k = 0; k < 64; k++) {
                float4 hv = __ldg(hp4 + (size_t)(pks * 64 + k) * 16);
                float  wv = wp[k];
                acc.x = fmaf(wv, hv.x, acc.x); acc.y = fmaf(wv, hv.y, acc.y);
                acc.z = fmaf(wv, hv.z, acc.z); acc.w = fmaf(wv, hv.w, acc.w);
            }
            *(float4*)&psumB[(pks * 2 + pwl) * 64 + pbg * 4] = acc;
        }
        __syncthreads();
        if (tid < 128) {
            const int b = tid & 63, wl = tid >> 6;
            float sacc = w2bs[wl];
#pragma unroll
            for (int ks = 0; ks < 8; ks++) sacc += psumB[(ks * 2 + wl) * 64 + b];
            d_blend2[b * 256 + 2 * blk + wl] = sacc;
        }
        grid_barrier(base + 3 * s + 2);

        // ---- C: scores[b][l] = tanh(blend1 + blend2) . vt ----
        {
            float4 b2a = __ldcg((const float4*)(d_blend2 + cb * 256) + lane);
            float4 b2b = __ldcg((const float4*)(d_blend2 + cb * 256) + 32 + lane);
            for (int li = 0; li < 32; li++) {
                const int l = lbase + li;
                const float4* bp = (const float4*)(d_blend1 + ((size_t)l * 64 + cb) * 256);
                float4 x = __ldg(bp + lane), y = __ldg(bp + 32 + lane);
                float sv = tanh_fast(x.x + b2a.x) * vta.x + tanh_fast(x.y + b2a.y) * vta.y
                         + tanh_fast(x.z + b2a.z) * vta.z + tanh_fast(x.w + b2a.w) * vta.w
                         + tanh_fast(y.x + b2b.x) * vtb.x + tanh_fast(y.y + b2b.y) * vtb.y
                         + tanh_fast(y.z + b2b.z) * vtb.z + tanh_fast(y.w + b2b.w) * vtb.w;
#pragma unroll
                for (int o = 16; o > 0; o >>= 1) sv += __shfl_xor_sync(0xFFFFFFFFu, sv, o);
                if (lane == 0) d_scores[cb * 512 + l] = sv;
            }
        }
        grid_barrier(base + 3 * s + 3);

        // ---- D: log-softmax over l (shuffle reduction), out[l][b][s] ----
        if (blk < 64) {
            float* red = psumB;
            const int b = blk;
            float s0 = __ldcg(d_scores + b * 512 + tid);
            float s1 = __ldcg(d_scores + b * 512 + tid + 256);
            float m = fmaxf(s0, s1);
#pragma unroll
            for (int o = 16; o > 0; o >>= 1) m = fmaxf(m, __shfl_xor_sync(0xFFFFFFFFu, m, o));
            if (lane == 0) red[wrp] = m;
            __syncthreads();
            float mm = red[0];
#pragma unroll
            for (int i = 1; i < 8; i++) mm = fmaxf(mm, red[i]);
            float se = __expf(s0 - mm) + __expf(s1 - mm);
#pragma unroll
            for (int o = 16; o > 0; o >>= 1) se += __shfl_xor_sync(0xFFFFFFFFu, se, o);
            if (lane == 0) red[8 + wrp] = se;
            __syncthreads();
            float tot = red[8];
#pragma unroll
            for (int i = 9; i < 16; i++) tot += red[i];
            const float lse = mm + __logf(tot);
            out[((size_t)tid         * 64 + b) * 64 + s] = s0 - lse;
            out[((size_t)(tid + 256) * 64 + b) * 64 + s] = s1 - lse;
        }
        __syncthreads();
    }
}

extern "C" void kernel_launch(void* const* d_in, const int* in_sizes, int n_in,
                              void* d_out, int out_size) {
    const int*   ids  = (const int*)  d_in[0];
    const float* emb  = (const float*)d_in[1];
    const float* eWih = (const float*)d_in[2];
    const float* eWhh = (const float*)d_in[3];
    const float* ebih = (const float*)d_in[4];
    const float* ebhh = (const float*)d_in[5];
    const float* dWhh = (const float*)d_in[7];
    const float* dbih = (const float*)d_in[8];
    const float* dbhh = (const float*)d_in[9];
    const float* W1w  = (const float*)d_in[10];
    const float* W1b  = (const float*)d_in[11];
    const float* W2w  = (const float*)d_in[12];
    const float* W2b  = (const float*)d_in[13];
    const float* vtw  = (const float*)d_in[14];
    const float* h0   = (const float*)d_in[16];
    float* out = (float*)d_out;

    cudaFuncSetAttribute(k_embproj, cudaFuncAttributeMaxDynamicSharedMemorySize, EP_SMEM);
    cudaFuncSetAttribute(k_blend1,  cudaFuncAttributeMaxDynamicSharedMemorySize, EP_SMEM);
    cudaFuncSetAttribute(k_encoder, cudaFuncAttributeMaxDynamicSharedMemorySize, ENC_SMEM);
    cudaFuncSetAttribute(k_decoder, cudaFuncAttributeMaxDynamicSharedMemorySize, DEC_SMEM);

    k_tofp16<<<1024, 256>>>(emb, eWih, W1w);
    dim3 g1(G_ / 64, (V_ + 127) / 128);
    k_embproj<<<g1, 256, EP_SMEM>>>(ebih, ebhh);
    k_encoder<<<NB, 256, ENC_SMEM>>>(ids, eWhh);
    dim3 g3(W_ / 64, (L_ * B_) / 128);
    k_blend1<<<g3, 256, EP_SMEM>>>(W1b);
    k_decoder<<<NB, 256, DEC_SMEM>>>(dWhh, dbih, dbhh, W2w, W2b, vtw, h0, out);
}

// round 17
// speedup vs baseline: 1.2140x; 1.0297x over previous
#include <cuda_runtime.h>
#include <cuda_fp16.h>
#include <cstdint>

#define L_ 512
#define T_ 64
#define H_ 512
#define B_ 64
#define E_ 256
#define W_ 256
#define V_ 10000
#define G_ 2048
#define NB 128

// ---- static scratch ----
__device__ float d_emb_proj[(size_t)V_ * G_];
__device__ float d_enc[(size_t)L_ * H_ * B_];     // fp32; only t=L-1 written (c0)
__device__ __half d_enc16[(size_t)L_ * B_ * H_];  // [(l*64+b)][h] fp16 (blend1 A)
__device__ __half d_blend1h[(size_t)L_ * B_ * W_]; // [l][b][w] fp16
__device__ float d_dhT[2][H_ * B_];               // [h][b] fp32 (decoder)
__device__ float d_blend2[B_ * W_];
__device__ float d_scores[B_ * L_];
__device__ unsigned d_count;
__device__ unsigned d_gen;
// packed h B-fragments (single fp16), double buffered
__device__ uint32_t d_eBp[2][16384];
__device__ uint32_t d_dBp[2][16384];
// fp16 weight/input copies for mma GEMMs
__device__ __half d_emb16[(size_t)V_ * E_];
__device__ __half d_wih16[(size_t)G_ * E_];
__device__ __half d_w1_16[(size_t)W_ * H_];

// SMEM maps (bytes) for encoder/decoder
#define SMO_FRAG  0          // 65536
#define SMO_PSUM  65536      // 32768
#define SMO_GSH   98304      // 4160
#define SMO_IDSA  102464
#define SMO_IDSB  102720
#define ENC_SMEM  102976
#define SMO_W2SH  102464
#define SMO_PSUMB 106560
#define SMO_W2BS  110656
#define SMO_BIAS  110664
#define DEC_SMEM  110728

// embproj/blend1 SMEM map (u32 word indices); row pitch 132 words
#define EP_PITCH 132
#define EP_A     0
#define EP_B     (128 * EP_PITCH)
#define EP_BIAS  (EP_B + 64 * EP_PITCH)
#define EP_SMEM  ((EP_BIAS + 64) * 4)

__device__ __forceinline__ float sigf(float x) { return 1.0f / (1.0f + __expf(-x)); }
__device__ __forceinline__ float tanh_acc(float x) {
    float e = __expf(2.0f * x);
    return 1.0f - 2.0f / (e + 1.0f);
}
__device__ __forceinline__ float tanh_fast(float x) {
    float r; asm("tanh.approx.f32 %0, %1;" : "=f"(r) : "f"(x)); return r;
}
__device__ __forceinline__ unsigned short fphi(float x) {
    return __half_as_ushort(__float2half_rn(x));
}
__device__ __forceinline__ float fp2f(unsigned short u) {
    return __half2float(__ushort_as_half(u));
}

__device__ __forceinline__ unsigned ld_gen_acq() {
    unsigned v;
    asm volatile("ld.acquire.gpu.global.u32 %0, [%1];" : "=r"(v) : "l"(&d_gen) : "memory");
    return v;
}
__device__ __forceinline__ void grid_barrier(unsigned target) {
    __syncthreads();
    if (threadIdx.x == 0) {
        unsigned prev;
        asm volatile("atom.add.release.gpu.global.u32 %0, [%1], 1;"
                     : "=r"(prev) : "l"(&d_count) : "memory");
        if (prev + 1 == target * NB) {
            asm volatile("st.release.gpu.global.u32 [%0], %1;"
                         :: "l"(&d_gen), "r"(target) : "memory");
        } else {
            while (ld_gen_acq() < target) { __nanosleep(32); }
        }
    }
    __syncthreads();
}

// D(16x8,f32) += A(16x16 fp16, row) x B(16x8 fp16, col)
__device__ __forceinline__ void mma_fp16(float* d, const uint32_t* a, uint32_t b0, uint32_t b1) {
    asm volatile(
        "mma.sync.aligned.m16n8k16.row.col.f32.f16.f16.f32 "
        "{%0,%1,%2,%3}, {%4,%5,%6,%7}, {%8,%9}, {%0,%1,%2,%3};"
        : "+f"(d[0]), "+f"(d[1]), "+f"(d[2]), "+f"(d[3])
        : "r"(a[0]), "r"(a[1]), "r"(a[2]), "r"(a[3]), "r"(b0), "r"(b1));
}

// Preload W fragments (A operand), fp16 hi/lo. Warp w owns chunks {w, w+8, w+16, w+24}.
__device__ __forceinline__ void preload_A(const float* __restrict__ Whh, int blk,
                                          int w, int g, int tig,
                                          uint32_t Ahi[4][4], uint32_t Alo[4][4]) {
#pragma unroll
    for (int i = 0; i < 4; i++) {
        const int c = w + 8 * i;
#pragma unroll
        for (int half = 0; half < 2; half++) {
            const int k = c * 16 + 2 * tig + half * 8;
#pragma unroll
            for (int rr = 0; rr < 2; rr++) {
                const int r = g + rr * 8;
                const int j = (r >> 2) * 512 + blk * 4 + (r & 3);
                float x0 = __ldg(Whh + (size_t)j * H_ + k);
                float x1 = __ldg(Whh + (size_t)j * H_ + k + 1);
                unsigned short h0 = fphi(x0), h1 = fphi(x1);
                unsigned short l0 = fphi(x0 - fp2f(h0)), l1 = fphi(x1 - fp2f(h1));
                Ahi[i][half * 2 + rr] = (uint32_t)h0 | ((uint32_t)h1 << 16);
                Alo[i][half * 2 + rr] = (uint32_t)l0 | ((uint32_t)l1 << 16);
            }
        }
    }
}

// Stage 64KB packed fragments in 2 commit groups.
__device__ __forceinline__ void stage_frag(const uint32_t* __restrict__ src,
                                           uint32_t smfrag, int tid) {
    const float4* s4 = (const float4*)src;
#pragma unroll
    for (int i = 0; i < 8; i++) {
        int idx = i * 256 + tid;
        asm volatile("cp.async.cg.shared.global [%0], [%1], 16;"
                     :: "r"(smfrag + idx * 16), "l"(s4 + idx));
    }
    asm volatile("cp.async.commit_group;");
#pragma unroll
    for (int i = 8; i < 16; i++) {
        int idx = i * 256 + tid;
        asm volatile("cp.async.cg.shared.global [%0], [%1], 16;"
                     :: "r"(smfrag + idx * 16), "l"(s4 + idx));
    }
    asm volatile("cp.async.commit_group;");
}

// MMA over 2 chunks starting at group i0.
__device__ __forceinline__ void compute_group(const uint32_t* frag, int w, int lane, int i0,
                                              const uint32_t Ahi[4][4], const uint32_t Alo[4][4],
                                              float D[8][4]) {
#pragma unroll
    for (int ii = 0; ii < 2; ii++) {
        const int i = i0 + ii;
        const uint32_t* fb = frag + (w + 8 * i) * 512;
#pragma unroll
        for (int nt = 0; nt < 8; nt++) {
            uint32_t b0 = fb[nt * 64 + lane];
            uint32_t b1 = fb[nt * 64 + 32 + lane];
            mma_fp16(D[nt], Ahi[i], b0, b1);
            mma_fp16(D[nt], Alo[i], b0, b1);
        }
    }
}

// Producer: pack this step's 4 h values as fp16 fragments.
__device__ __forceinline__ void pack_h(uint32_t* __restrict__ dst, int blk, int b,
                                       const float* hv) {
    const int chunk = blk >> 2, q = blk & 3;
    const int reg = (q >= 2) ? 1 : 0;
    const int p0 = q * 2;
    const int tig0 = p0 & 3, tig1 = (p0 + 1) & 3;
    const int lb = (b & 7) * 4;
    unsigned short h[4];
#pragma unroll
    for (int c2 = 0; c2 < 4; c2++) h[c2] = fphi(hv[c2]);
    const uint32_t base = chunk * 512 + (b >> 3) * 64 + reg * 32;
    dst[base + lb + tig0] = (uint32_t)h[0] | ((uint32_t)h[1] << 16);
    dst[base + lb + tig1] = (uint32_t)h[2] | ((uint32_t)h[3] << 16);
}

// Reduce per-warp D partials into gsh[r*65+b].
__device__ __forceinline__ void reduce_gates(float* psum, float* gsh, float D[8][4],
                                             int w, int g, int tig, int tid) {
#pragma unroll
    for (int nt = 0; nt < 8; nt++) {
        *(float2*)&psum[(w * 16 + g) * 64 + nt * 8 + 2 * tig]     = make_float2(D[nt][0], D[nt][1]);
        *(float2*)&psum[(w * 16 + g + 8) * 64 + nt * 8 + 2 * tig] = make_float2(D[nt][2], D[nt][3]);
    }
    __syncthreads();
    const int rr = tid >> 4, b4 = (tid & 15) * 4;
    float4 acc = *(const float4*)&psum[rr * 64 + b4];
#pragma unroll
    for (int w2 = 1; w2 < 8; w2++) {
        float4 v = *(const float4*)&psum[(w2 * 16 + rr) * 64 + b4];
        acc.x += v.x; acc.y += v.y; acc.z += v.z; acc.w += v.w;
    }
    gsh[rr * 65 + b4 + 0] = acc.x;
    gsh[rr * 65 + b4 + 1] = acc.y;
    gsh[rr * 65 + b4 + 2] = acc.z;
    gsh[rr * 65 + b4 + 3] = acc.w;
    __syncthreads();
}

// ============ K0: fp16 conversions ============
__global__ void __launch_bounds__(256) k_tofp16(
    const float* __restrict__ emb, const float* __restrict__ Wih,
    const float* __restrict__ W1w)
{
    const size_t nE = (size_t)V_ * E_;
    const size_t nW = (size_t)G_ * E_;
    const size_t nW1 = (size_t)W_ * H_;
    for (size_t i = (size_t)blockIdx.x * 256 + threadIdx.x; i < nE + nW + nW1;
         i += (size_t)gridDim.x * 256) {
        if (i < nE)            d_emb16[i] = __float2half_rn(emb[i]);
        else if (i < nE + nW)  d_wih16[i - nE] = __float2half_rn(Wih[i - nE]);
        else                   d_w1_16[i - nE - nW] = __float2half_rn(W1w[i - nE - nW]);
    }
}

// ============ K1: emb_proj = emb @ Wih^T + bih + bhh (fp16 mma) ============
__global__ void __launch_bounds__(256) k_embproj(
    const float* __restrict__ bih, const float* __restrict__ bhh)
{
    extern __shared__ __align__(16) uint32_t eps[];
    uint32_t* Ash = eps + EP_A;
    uint32_t* Bsh = eps + EP_B;
    float*    bsh = (float*)(eps + EP_BIAS);
    const uint32_t smb = (uint32_t)__cvta_generic_to_shared(eps);

    const int tid = threadIdx.x;
    const int j0 = blockIdx.x * 64, v0 = blockIdx.y * 128;
    const int lane = tid & 31, w = tid >> 5;
    const int g = lane >> 2, tig = lane & 3;

#pragma unroll
    for (int it = 0; it < 16; it++) {
        const int c = it * 256 + tid;
        const int row = c >> 5, ch = c & 31;
        int v = v0 + row;
        unsigned bytes = (v < V_) ? 16u : 0u;
        if (v >= V_) v = 0;
        const __half* src = d_emb16 + (size_t)v * E_ + ch * 8;
        asm volatile("cp.async.cg.shared.global [%0], [%1], 16, %2;"
                     :: "r"(smb + (EP_A + row * EP_PITCH + ch * 4) * 4), "l"(src), "r"(bytes));
    }
#pragma unroll
    for (int it = 0; it < 8; it++) {
        const int c = it * 256 + tid;
        const int row = c >> 5, ch = c & 31;
        const __half* src = d_wih16 + (size_t)(j0 + row) * E_ + ch * 8;
        asm volatile("cp.async.cg.shared.global [%0], [%1], 16;"
                     :: "r"(smb + (EP_B + row * EP_PITCH + ch * 4) * 4), "l"(src));
    }
    asm volatile("cp.async.commit_group;");
    if (tid < 64) bsh[tid] = __ldg(bih + j0 + tid) + __ldg(bhh + j0 + tid);
    asm volatile("cp.async.wait_group 0;" ::: "memory");
    __syncthreads();

    const int rb = w * 16;
    float D[8][4];
#pragma unroll
    for (int nt = 0; nt < 8; nt++)
#pragma unroll
        for (int i = 0; i < 4; i++) D[nt][i] = 0.0f;

#pragma unroll
    for (int kt = 0; kt < 16; kt++) {
        uint32_t a[4];
        a[0] = Ash[(rb + g)     * EP_PITCH + kt * 8 + tig];
        a[1] = Ash[(rb + g + 8) * EP_PITCH + kt * 8 + tig];
        a[2] = Ash[(rb + g)     * EP_PITCH + kt * 8 + tig + 4];
        a[3] = Ash[(rb + g + 8) * EP_PITCH + kt * 8 + tig + 4];
#pragma unroll
        for (int nt = 0; nt < 8; nt++) {
            uint32_t b0 = Bsh[(nt * 8 + g) * EP_PITCH + kt * 8 + tig];
            uint32_t b1 = Bsh[(nt * 8 + g) * EP_PITCH + kt * 8 + tig + 4];
            mma_fp16(D[nt], a, b0, b1);
        }
    }

#pragma unroll
    for (int nt = 0; nt < 8; nt++) {
        const int jl = nt * 8 + 2 * tig;
        const float b0 = bsh[jl], b1 = bsh[jl + 1];
        const int v1 = v0 + rb + g, v2 = v1 + 8;
        if (v1 < V_)
            *(float2*)&d_emb_proj[(size_t)v1 * G_ + j0 + jl] =
                make_float2(D[nt][0] + b0, D[nt][1] + b1);
        if (v2 < V_)
            *(float2*)&d_emb_proj[(size_t)v2 * G_ + j0 + jl] =
                make_float2(D[nt][2] + b0, D[nt][3] + b1);
    }
}

// ============ K2: persistent encoder (mma.sync fp16 W-split) ============
__global__ void __launch_bounds__(256, 1) k_encoder(
    const int* __restrict__ ids, const float* __restrict__ Whh)
{
    extern __shared__ __align__(16) char sm[];
    uint32_t* frag = (uint32_t*)(sm + SMO_FRAG);
    float*    psum = (float*)(sm + SMO_PSUM);
    float*    gsh  = (float*)(sm + SMO_GSH);
    int*      idsA = (int*)(sm + SMO_IDSA);
    int*      idsB = (int*)(sm + SMO_IDSB);

    const int tid = threadIdx.x, blk = blockIdx.x;
    const int lane = tid & 31, w = tid >> 5;
    const int g = lane >> 2, tig = lane & 3;
    const uint32_t smfrag = (uint32_t)__cvta_generic_to_shared(frag);
    unsigned g0 = 0;
    if (tid == 0) g0 = ld_gen_acq();

    uint32_t Ahi[4][4], Alo[4][4];
    preload_A(Whh, blk, w, g, tig, Ahi, Alo);
    if (tid < 64) idsA[tid] = __ldg(ids + tid * L_);
    float cc[4] = {0.f, 0.f, 0.f, 0.f};
    __syncthreads();

    for (int t = 0; t < L_; t++) {
        int* cur_ids = (t & 1) ? idsB : idsA;
        int* nxt_ids = (t & 1) ? idsA : idsB;
        if (t > 0) stage_frag(d_eBp[(t - 1) & 1], smfrag, tid);
        float ei[4], ef[4], eg[4], eo[4];
        if (tid < 64) {
            const float4* ep = (const float4*)(d_emb_proj + (size_t)cur_ids[tid] * G_);
            float4 x0 = __ldg(ep + blk);
            float4 x1 = __ldg(ep + 128 + blk);
            float4 x2 = __ldg(ep + 256 + blk);
            float4 x3 = __ldg(ep + 384 + blk);
            ei[0]=x0.x; ei[1]=x0.y; ei[2]=x0.z; ei[3]=x0.w;
            ef[0]=x1.x; ef[1]=x1.y; ef[2]=x1.z; ef[3]=x1.w;
            eg[0]=x2.x; eg[1]=x2.y; eg[2]=x2.z; eg[3]=x2.w;
            eo[0]=x3.x; eo[1]=x3.y; eo[2]=x3.z; eo[3]=x3.w;
            if (t + 1 < L_) nxt_ids[tid] = __ldg(ids + tid * L_ + t + 1);
        }

        if (t > 0) {
            float D[8][4];
#pragma unroll
            for (int nt = 0; nt < 8; nt++)
#pragma unroll
                for (int i = 0; i < 4; i++) D[nt][i] = 0.0f;
            asm volatile("cp.async.wait_group 1;" ::: "memory");
            __syncthreads();
            compute_group(frag, w, lane, 0, Ahi, Alo, D);
            asm volatile("cp.async.wait_group 0;" ::: "memory");
            __syncthreads();
            compute_group(frag, w, lane, 2, Ahi, Alo, D);
            reduce_gates(psum, gsh, D, w, g, tig, tid);
        }

        if (tid < 64) {
            const int b = tid;
            float hv[4];
            unsigned long long pk = 0;
#pragma unroll
            for (int cell = 0; cell < 4; cell++) {
                float gi = ((t > 0) ? gsh[(0  + cell) * 65 + b] : 0.f) + ei[cell];
                float gf = ((t > 0) ? gsh[(4  + cell) * 65 + b] : 0.f) + ef[cell];
                float gg = ((t > 0) ? gsh[(8  + cell) * 65 + b] : 0.f) + eg[cell];
                float go = ((t > 0) ? gsh[(12 + cell) * 65 + b] : 0.f) + eo[cell];
                cc[cell] = sigf(gf) * cc[cell] + sigf(gi) * tanh_acc(gg);
                float h = sigf(go) * tanh_acc(cc[cell]);
                if (t == L_ - 1)
                    d_enc[(size_t)t * H_ * B_ + (blk * 4 + cell) * 64 + b] = h;
                hv[cell] = h;
                pk |= (unsigned long long)fphi(h) << (cell * 16);
            }
            *(unsigned long long*)(d_enc16 + ((size_t)t * 64 + b) * 512 + blk * 4) = pk;
            pack_h(d_eBp[t & 1], blk, b, hv);
        }
        if (t + 1 < L_) grid_barrier(g0 + t + 1);
    }
}

// ============ K3: blend1 via fp16 mma, fp16 output ============
__global__ void __launch_bounds__(256) k_blend1(const float* __restrict__ W1b)
{
    extern __shared__ __align__(16) uint32_t eps[];
    uint32_t* Ash = eps + EP_A;
    uint32_t* Bsh = eps + EP_B;
    float*    bsh = (float*)(eps + EP_BIAS);
    const uint32_t smb = (uint32_t)__cvta_generic_to_shared(eps);

    const int tid = threadIdx.x;
    const int j0 = blockIdx.x * 64;
    const int v0 = blockIdx.y * 128;
    const int lane = tid & 31, w = tid >> 5;
    const int g = lane >> 2, tig = lane & 3;
    const int rb = w * 16;

    if (tid < 64) bsh[tid] = __ldg(W1b + j0 + tid);

    float D[8][4];
#pragma unroll
    for (int nt = 0; nt < 8; nt++)
#pragma unroll
        for (int i = 0; i < 4; i++) D[nt][i] = 0.0f;

#pragma unroll
    for (int p = 0; p < 2; p++) {
        const int k0 = p * 256;
#pragma unroll
        for (int it = 0; it < 16; it++) {
            const int c = it * 256 + tid;
            const int row = c >> 5, ch = c & 31;
            const __half* src = d_enc16 + (size_t)(v0 + row) * H_ + k0 + ch * 8;
            asm volatile("cp.async.cg.shared.global [%0], [%1], 16;"
                         :: "r"(smb + (EP_A + row * EP_PITCH + ch * 4) * 4), "l"(src));
        }
#pragma unroll
        for (int it = 0; it < 8; it++) {
            const int c = it * 256 + tid;
            const int row = c >> 5, ch = c & 31;
            const __half* src = d_w1_16 + (size_t)(j0 + row) * H_ + k0 + ch * 8;
            asm volatile("cp.async.cg.shared.global [%0], [%1], 16;"
                         :: "r"(smb + (EP_B + row * EP_PITCH + ch * 4) * 4), "l"(src));
        }
        asm volatile("cp.async.commit_group;");
        asm volatile("cp.async.wait_group 0;" ::: "memory");
        __syncthreads();

#pragma unroll
        for (int kt = 0; kt < 16; kt++) {
            uint32_t a[4];
            a[0] = Ash[(rb + g)     * EP_PITCH + kt * 8 + tig];
            a[1] = Ash[(rb + g + 8) * EP_PITCH + kt * 8 + tig];
            a[2] = Ash[(rb + g)     * EP_PITCH + kt * 8 + tig + 4];
            a[3] = Ash[(rb + g + 8) * EP_PITCH + kt * 8 + tig + 4];
#pragma unroll
            for (int nt = 0; nt < 8; nt++) {
                uint32_t b0 = Bsh[(nt * 8 + g) * EP_PITCH + kt * 8 + tig];
                uint32_t b1 = Bsh[(nt * 8 + g) * EP_PITCH + kt * 8 + tig + 4];
                mma_fp16(D[nt], a, b0, b1);
            }
        }
        __syncthreads();
    }

#pragma unroll
    for (int nt = 0; nt < 8; nt++) {
        const int jl = nt * 8 + 2 * tig;
        const float b0 = bsh[jl], b1 = bsh[jl + 1];
        const int r1 = v0 + rb + g, r2 = r1 + 8;
        uint32_t o1 = (uint32_t)fphi(D[nt][0] + b0) | ((uint32_t)fphi(D[nt][1] + b1) << 16);
        uint32_t o2 = (uint32_t)fphi(D[nt][2] + b0) | ((uint32_t)fphi(D[nt][3] + b1) << 16);
        *(uint32_t*)&d_blend1h[(size_t)r1 * W_ + j0 + jl] = o1;
        *(uint32_t*)&d_blend1h[(size_t)r2 * W_ + j0 + jl] = o2;
    }
}

// ============ K4: persistent decoder ============
__global__ void __launch_bounds__(256, 1) k_decoder(
    const float* __restrict__ Whh, const float* __restrict__ bih,
    const float* __restrict__ bhh, const float* __restrict__ W2w,
    const float* __restrict__ W2b, const float* __restrict__ vtw,
    const float* __restrict__ h0, float* __restrict__ out)
{
    extern __shared__ __align__(16) char sm[];
    uint32_t* frag  = (uint32_t*)(sm + SMO_FRAG);
    float*    psum  = (float*)(sm + SMO_PSUM);
    float*    gsh   = (float*)(sm + SMO_GSH);
    float*    w2sh  = (float*)(sm + SMO_W2SH);
    float*    psumB = (float*)(sm + SMO_PSUMB);
    float*    w2bs  = (float*)(sm + SMO_W2BS);
    float*    bias_sh = (float*)(sm + SMO_BIAS);

    const int tid = threadIdx.x, blk = blockIdx.x;
    const int lane = tid & 31, w = tid >> 5;
    const int g = lane >> 2, tig = lane & 3;
    const uint32_t smfrag = (uint32_t)__cvta_generic_to_shared(frag);
    unsigned g0 = 0;
    if (tid == 0) g0 = ld_gen_acq();

    uint32_t Ahi[4][4], Alo[4][4];
    preload_A(Whh, blk, w, g, tig, Ahi, Alo);
    if (tid < 16) {
        const int j = (tid >> 2) * 512 + blk * 4 + (tid & 3);
        bias_sh[tid] = __ldg(bih + j) + __ldg(bhh + j);
    }
    for (int idx = tid; idx < 1024; idx += 256) {
        const int row = idx >> 9, hh = idx & 511;
        w2sh[idx] = __ldg(W2w + (size_t)(2 * blk + row) * H_ + hh);
    }
    if (tid < 2) w2bs[tid] = __ldg(W2b + 2 * blk + tid);
    float cc[4] = {0.f, 0.f, 0.f, 0.f};
    if (tid < 64) {
        float hv[4];
#pragma unroll
        for (int cell = 0; cell < 4; cell++) {
            float x = __ldg(h0 + (size_t)tid * H_ + blk * 4 + cell);
            d_dhT[0][(blk * 4 + cell) * 64 + tid] = x;
            hv[cell] = x;
            cc[cell] = __ldg(d_enc + (size_t)(L_ - 1) * H_ * B_ + (blk * 4 + cell) * 64 + tid);
        }
        pack_h(d_dBp[0], blk, tid, hv);
    }
    const int wrp = w;
    const int gw = blk * 8 + wrp;
    const int cb = gw & 63, lbase = (gw >> 6) * 32;
    const float4 vta = __ldg((const float4*)vtw + 2 * lane);
    const float4 vtb = __ldg((const float4*)vtw + 2 * lane + 1);
    const int pbg = tid & 15, pwl = (tid >> 4) & 1, pks = tid >> 5;

    grid_barrier(g0 + 1);
    const unsigned base = g0 + 1;

    for (int s = 0; s < T_; s++) {
        const int cur = s & 1, nxt = cur ^ 1;

        // ---- A: recurrent gates via mma.sync ----
        {
            stage_frag(d_dBp[cur], smfrag, tid);
            float D[8][4];
#pragma unroll
            for (int nt = 0; nt < 8; nt++)
#pragma unroll
                for (int i = 0; i < 4; i++) D[nt][i] = 0.0f;
            asm volatile("cp.async.wait_group 1;" ::: "memory");
            __syncthreads();
            compute_group(frag, w, lane, 0, Ahi, Alo, D);
            asm volatile("cp.async.wait_group 0;" ::: "memory");
            __syncthreads();
            compute_group(frag, w, lane, 2, Ahi, Alo, D);
            reduce_gates(psum, gsh, D, w, g, tig, tid);
        }
        if (tid < 64) {
            const int b = tid;
            float hv[4];
#pragma unroll
            for (int cell = 0; cell < 4; cell++) {
                float gi = gsh[(0  + cell) * 65 + b] + bias_sh[cell];
                float gf = gsh[(4  + cell) * 65 + b] + bias_sh[4 + cell];
                float gg = gsh[(8  + cell) * 65 + b] + bias_sh[8 + cell];
                float go = gsh[(12 + cell) * 65 + b] + bias_sh[12 + cell];
                cc[cell] = sigf(gf) * cc[cell] + sigf(gi) * tanh_acc(gg);
                float h = sigf(go) * tanh_acc(cc[cell]);
                d_dhT[nxt][(blk * 4 + cell) * 64 + b] = h;
                hv[cell] = h;
            }
            pack_h(d_dBp[nxt], blk, b, hv);
        }
        grid_barrier(base + 3 * s + 1);

        // ---- B: blend2 rows 2*blk, 2*blk+1 (k-split __ldg) ----
        {
            const float4* hp4 = (const float4*)d_dhT[nxt] + pbg;
            const float* wp = w2sh + pwl * 512 + pks * 64;
            float4 acc = make_float4(0.f, 0.f, 0.f, 0.f);
#pragma unroll 8
            for (int k = 0; k < 64; k++) {
                float4 hv = __ldg(hp4 + (size_t)(pks * 64 + k) * 16);
                float  wv = wp[k];
                acc.x = fmaf(wv, hv.x, acc.x); acc.y = fmaf(wv, hv.y, acc.y);
                acc.z = fmaf(wv, hv.z, acc.z); acc.w = fmaf(wv, hv.w, acc.w);
            }
            *(float4*)&psumB[(pks * 2 + pwl) * 64 + pbg * 4] = acc;
        }
        __syncthreads();
        if (tid < 128) {
            const int b = tid & 63, wl = tid >> 6;
            float sacc = w2bs[wl];
#pragma unroll
            for (int ks = 0; ks < 8; ks++) sacc += psumB[(ks * 2 + wl) * 64 + b];
            d_blend2[b * 256 + 2 * blk + wl] = sacc;
        }
        grid_barrier(base + 3 * s + 2);

        // ---- C: scores[b][l] = tanh(blend1h + blend2) . vt  (fp16 blend1) ----
        {
            float4 b2a = __ldcg((const float4*)(d_blend2 + cb * 256) + 2 * lane);
            float4 b2b = __ldcg((const float4*)(d_blend2 + cb * 256) + 2 * lane + 1);
            for (int li = 0; li < 32; li++) {
                const int l = lbase + li;
                uint4 p = __ldg((const uint4*)(d_blend1h + ((size_t)l * 64 + cb) * 256) + lane);
                float f0 = fp2f((unsigned short)(p.x & 0xFFFF));
                float f1 = fp2f((unsigned short)(p.x >> 16));
                float f2 = fp2f((unsigned short)(p.y & 0xFFFF));
                float f3 = fp2f((unsigned short)(p.y >> 16));
                float f4 = fp2f((unsigned short)(p.z & 0xFFFF));
                float f5 = fp2f((unsigned short)(p.z >> 16));
                float f6 = fp2f((unsigned short)(p.w & 0xFFFF));
                float f7 = fp2f((unsigned short)(p.w >> 16));
                float sv = tanh_fast(f0 + b2a.x) * vta.x + tanh_fast(f1 + b2a.y) * vta.y
                         + tanh_fast(f2 + b2a.z) * vta.z + tanh_fast(f3 + b2a.w) * vta.w
                         + tanh_fast(f4 + b2b.x) * vtb.x + tanh_fast(f5 + b2b.y) * vtb.y
                         + tanh_fast(f6 + b2b.z) * vtb.z + tanh_fast(f7 + b2b.w) * vtb.w;
#pragma unroll
                for (int o = 16; o > 0; o >>= 1) sv += __shfl_xor_sync(0xFFFFFFFFu, sv, o);
                if (lane == 0) d_scores[cb * 512 + l] = sv;
            }
        }
        grid_barrier(base + 3 * s + 3);

        // ---- D: log-softmax over l (shuffle reduction), out[l][b][s] ----
        if (blk < 64) {
            float* red = psumB;
            const int b = blk;
            float s0 = __ldcg(d_scores + b * 512 + tid);
            float s1 = __ldcg(d_scores + b * 512 + tid + 256);
            float m = fmaxf(s0, s1);
#pragma unroll
            for (int o = 16; o > 0; o >>= 1) m = fmaxf(m, __shfl_xor_sync(0xFFFFFFFFu, m, o));
            if (lane == 0) red[wrp] = m;
            __syncthreads();
            float mm = red[0];
#pragma unroll
            for (int i = 1; i < 8; i++) mm = fmaxf(mm, red[i]);
            float se = __expf(s0 - mm) + __expf(s1 - mm);
#pragma unroll
            for (int o = 16; o > 0; o >>= 1) se += __shfl_xor_sync(0xFFFFFFFFu, se, o);
            if (lane == 0) red[8 + wrp] = se;
            __syncthreads();
            float tot = red[8];
#pragma unroll
            for (int i = 9; i < 16; i++) tot += red[i];
            const float lse = mm + __logf(tot);
            out[((size_t)tid         * 64 + b) * 64 + s] = s0 - lse;
            out[((size_t)(tid + 256) * 64 + b) * 64 + s] = s1 - lse;
        }
        __syncthreads();
    }
}

extern "C" void kernel_launch(void* const* d_in, const int* in_sizes, int n_in,
                              void* d_out, int out_size) {
    const int*   ids  = (const int*)  d_in[0];
    const float* emb  = (const float*)d_in[1];
    const float* eWih = (const float*)d_in[2];
    const float* eWhh = (const float*)d_in[3];
    const float* ebih = (const float*)d_in[4];
    const float* ebhh = (const float*)d_in[5];
    const float* dWhh = (const float*)d_in[7];
    const float* dbih = (const float*)d_in[8];
    const float* dbhh = (const float*)d_in[9];
    const float* W1w  = (const float*)d_in[10];
    const float* W1b  = (const float*)d_in[11];
    const float* W2w  = (const float*)d_in[12];
    const float* W2b  = (const float*)d_in[13];
    const float* vtw  = (const float*)d_in[14];
    const float* h0   = (const float*)d_in[16];
    float* out = (float*)d_out;

    cudaFuncSetAttribute(k_embproj, cudaFuncAttributeMaxDynamicSharedMemorySize, EP_SMEM);
    cudaFuncSetAttribute(k_blend1,  cudaFuncAttributeMaxDynamicSharedMemorySize, EP_SMEM);
    cudaFuncSetAttribute(k_encoder, cudaFuncAttributeMaxDynamicSharedMemorySize, ENC_SMEM);
    cudaFuncSetAttribute(k_decoder, cudaFuncAttributeMaxDynamicSharedMemorySize, DEC_SMEM);

    k_tofp16<<<1024, 256>>>(emb, eWih, W1w);
    dim3 g1(G_ / 64, (V_ + 127) / 128);
    k_embproj<<<g1, 256, EP_SMEM>>>(ebih, ebhh);
    k_encoder<<<NB, 256, ENC_SMEM>>>(ids, eWhh);
    dim3 g3(W_ / 64, (L_ * B_) / 128);
    k_blend1<<<g3, 256, EP_SMEM>>>(W1b);
    k_decoder<<<NB, 256, DEC_SMEM>>>(dWhh, dbih, dbhh, W2w, W2b, vtw, h0, out);
}